// round 1
// baseline (speedup 1.0000x reference)
#include <cuda_runtime.h>
#include <math.h>

#define NROWS 65536
#define PER   64
#define NBLK  1024          // NROWS / PER
#define NC    36
#define OBJ   192
#define EMB   200
#define POSD  128
#define HID   1024
#define KEFF  355           // 192 + 35 + 128
#define KP    368           // padded to multiple of 16
#define EPS   1e-5f

// ---------------- device scratch (static allocation is the sanctioned path) ----------------
__device__ float d_A[(size_t)NROWS * KP];     // fused input matrix [N, KP]
__device__ float d_W[(size_t)KP * HID];       // folded dec1 weights [KP, HID]
__device__ float d_b1[HID];                   // folded dec1 bias (bn folded)
__device__ float d_a[HID];                    // bn1k scale
__device__ float d_PW[4 * POSD];              // folded pos weights
__device__ float d_pb[POSD];                  // folded pos bias
__device__ float d_g[(size_t)HID * NROWS];    // hidden activations, TRANSPOSED [k][row]

// ---------------- prep kernels (tiny) ----------------
__global__ void k_prep_a(const float* __restrict__ g, const float* __restrict__ b,
                         const float* __restrict__ m, const float* __restrict__ v,
                         const float* __restrict__ dec1_b) {
    int j = blockIdx.x * blockDim.x + threadIdx.x;
    if (j < HID) {
        float a = g[j] * rsqrtf(v[j] + EPS);
        float c = b[j] - m[j] * a;
        d_a[j]  = a;
        d_b1[j] = dec1_b[j] * a + c;
    }
}

__global__ void k_prep_pos(const float* __restrict__ g4, const float* __restrict__ b4,
                           const float* __restrict__ m4, const float* __restrict__ v4,
                           const float* __restrict__ pos_W, const float* __restrict__ pos_b) {
    int j = threadIdx.x;  // 128
    float s[4], t[4];
#pragma unroll
    for (int k = 0; k < 4; k++) {
        s[k] = g4[k] * rsqrtf(v4[k] + EPS);
        t[k] = b4[k] - m4[k] * s[k];
    }
    float pb = pos_b[j];
#pragma unroll
    for (int k = 0; k < 4; k++) {
        float w = pos_W[k * POSD + j];
        d_PW[k * POSD + j] = s[k] * w;
        pb += t[k] * w;
    }
    d_pb[j] = pb;
}

// scale dec1 weight columns by a[j]; features rows 0..191, pos rows 227..354; zero pad rows
__global__ void k_scale_w(const float* __restrict__ dec1_W) {
    int idx = blockIdx.x * blockDim.x + threadIdx.x;
    if (idx >= KP * HID) return;
    int k = idx / HID, j = idx % HID;
    if (k >= OBJ && k < OBJ + 35) return;  // filled by k_m1
    float v;
    if (k < OBJ)       v = dec1_W[(size_t)k * HID + j] * d_a[j];
    else if (k < KEFF) v = dec1_W[(size_t)(OBJ + EMB + (k - (OBJ + 35))) * HID + j] * d_a[j];
    else               v = 0.f;
    d_W[idx] = v;
}

// M1 = obj_embed_W(35x200) @ dec1_W[192:392] scaled by a[j]
__global__ void k_m1(const float* __restrict__ obj_embed_W, const float* __restrict__ dec1_W) {
    int idx = blockIdx.x * blockDim.x + threadIdx.x;
    if (idx >= 35 * HID) return;
    int e = idx / HID, j = idx % HID;
    float s = 0.f;
#pragma unroll 4
    for (int k = 0; k < EMB; k++)
        s += obj_embed_W[e * EMB + k] * dec1_W[(size_t)(OBJ + k) * HID + j];
    d_W[(size_t)(OBJ + e) * HID + j] = s * d_a[j];
}

// build fused A matrix per row: [features(192) | distribution(35) | pos(128) | pad(13)]
__global__ void k_buildA(const float* __restrict__ features,
                         const float* __restrict__ distribution,
                         const float* __restrict__ boxes) {
    int r = blockIdx.x;
    int j = threadIdx.x;  // 128
    float* Arow = &d_A[(size_t)r * KP];
    Arow[j] = features[(size_t)r * OBJ + j];
    if (j < 64) Arow[128 + j] = features[(size_t)r * OBJ + 128 + j];
    if (j < 35) Arow[OBJ + j] = distribution[(size_t)r * 35 + j];
    if (j >= 35 && j < 48) Arow[320 + j] = 0.f;  // pad cols 355..367

    float x1 = boxes[(size_t)r * 5 + 1], y1 = boxes[(size_t)r * 5 + 2];
    float x2 = boxes[(size_t)r * 5 + 3], y2 = boxes[(size_t)r * 5 + 4];
    float w = x2 - x1 + 1.f, h = y2 - y1 + 1.f;
    float c0 = x1 + 0.5f * w, c1 = y1 + 0.5f * h;
    float p = d_pb[j] + c0 * d_PW[j] + c1 * d_PW[POSD + j]
                     + w  * d_PW[2 * POSD + j] + h * d_PW[3 * POSD + j];
    Arow[OBJ + 35 + j] = fmaxf(p, 0.f);
}

// ---------------- GEMM1: g^T = relu(A @ W + b1), C written transposed ----------------
#define BM 128
#define BN 128
#define BK 16

__global__ __launch_bounds__(256) void k_gemm1() {
    __shared__ float As[BK][BM];
    __shared__ float Bs[BK][BN];
    int t  = threadIdx.x;
    int ty = t & 15;   // row sub-tile
    int tx = t >> 4;   // col sub-tile
    int i0 = blockIdx.y * BM;
    int j0 = blockIdx.x * BN;

    float acc[8][8];
#pragma unroll
    for (int r = 0; r < 8; r++)
#pragma unroll
        for (int c = 0; c < 8; c++) acc[r][c] = 0.f;

    int ar = t >> 2;            // 0..63
    int ak = (t & 3) * 4;       // 0,4,8,12
    int br = t >> 4;            // 0..15
    int bc = (t & 15) * 8;      // 0..120

    for (int kb = 0; kb < KP; kb += BK) {
        float4 v0 = *(const float4*)&d_A[(size_t)(i0 + ar) * KP + kb + ak];
        float4 v1 = *(const float4*)&d_A[(size_t)(i0 + 64 + ar) * KP + kb + ak];
        As[ak + 0][ar] = v0.x; As[ak + 1][ar] = v0.y; As[ak + 2][ar] = v0.z; As[ak + 3][ar] = v0.w;
        As[ak + 0][64 + ar] = v1.x; As[ak + 1][64 + ar] = v1.y;
        As[ak + 2][64 + ar] = v1.z; As[ak + 3][64 + ar] = v1.w;

        const float* src = &d_W[(size_t)(kb + br) * HID + j0 + bc];
        *(float4*)&Bs[br][bc]     = *(const float4*)src;
        *(float4*)&Bs[br][bc + 4] = *(const float4*)(src + 4);
        __syncthreads();

#pragma unroll
        for (int kk = 0; kk < BK; kk++) {
            float4 a0 = *(float4*)&As[kk][ty * 4];
            float4 a1 = *(float4*)&As[kk][64 + ty * 4];
            float4 b0 = *(float4*)&Bs[kk][tx * 4];
            float4 b1 = *(float4*)&Bs[kk][64 + tx * 4];
            float av[8] = {a0.x, a0.y, a0.z, a0.w, a1.x, a1.y, a1.z, a1.w};
            float bv[8] = {b0.x, b0.y, b0.z, b0.w, b1.x, b1.y, b1.z, b1.w};
#pragma unroll
            for (int r = 0; r < 8; r++)
#pragma unroll
                for (int c = 0; c < 8; c++) acc[r][c] += av[r] * bv[c];
        }
        __syncthreads();
    }

    // epilogue: bias + relu, write transposed (coalesced float4 over rows)
#pragma unroll
    for (int c = 0; c < 8; c++) {
        int j = j0 + ((c < 4) ? (tx * 4 + c) : (64 + tx * 4 + c - 4));
        float bj = d_b1[j];
        float* base = &d_g[(size_t)j * NROWS + i0 + ty * 4];
        float4 o0, o1;
        o0.x = fmaxf(acc[0][c] + bj, 0.f); o0.y = fmaxf(acc[1][c] + bj, 0.f);
        o0.z = fmaxf(acc[2][c] + bj, 0.f); o0.w = fmaxf(acc[3][c] + bj, 0.f);
        o1.x = fmaxf(acc[4][c] + bj, 0.f); o1.y = fmaxf(acc[5][c] + bj, 0.f);
        o1.z = fmaxf(acc[6][c] + bj, 0.f); o1.w = fmaxf(acc[7][c] + bj, 0.f);
        *(float4*)base        = o0;
        *(float4*)(base + 64) = o1;
    }
}

// ---------------- pass2: logits + softmax + pred (one row per thread, W2 in SMEM) ----------------
__global__ __launch_bounds__(256) void k_pass2(const float* __restrict__ dec2_W,
                                               const float* __restrict__ dec2_b,
                                               float* __restrict__ out) {
    extern __shared__ float Ws[];  // 1024*36
    int t = threadIdx.x;
    for (int i = t; i < HID * NC / 4; i += 256)
        ((float4*)Ws)[i] = ((const float4*)dec2_W)[i];
    __syncthreads();

    int r = blockIdx.x * 256 + t;
    float acc[NC];
#pragma unroll
    for (int c = 0; c < NC; c++) acc[c] = dec2_b[c];

#pragma unroll 4
    for (int k = 0; k < HID; k++) {
        float v = d_g[(size_t)k * NROWS + r];
        const float4* wr = (const float4*)&Ws[k * NC];
#pragma unroll
        for (int c4 = 0; c4 < NC / 4; c4++) {
            float4 w = wr[c4];
            acc[c4 * 4 + 0] += v * w.x;
            acc[c4 * 4 + 1] += v * w.y;
            acc[c4 * 4 + 2] += v * w.z;
            acc[c4 * 4 + 3] += v * w.w;
        }
    }

    // softmax over logits[1..35]
    float m = acc[1];
#pragma unroll
    for (int c = 2; c < NC; c++) m = fmaxf(m, acc[c]);
    float e[35], s = 0.f;
#pragma unroll
    for (int i = 0; i < 35; i++) { e[i] = expf(acc[1 + i] - m); s += e[i]; }
    float inv = 1.f / s;
#pragma unroll
    for (int i = 0; i < 35; i++) out[(size_t)r * 35 + i] = e[i] * inv;

    // pred over dist cols 1..34 (first max)
    float best = e[1]; int bi = 1;
#pragma unroll
    for (int i = 2; i < 35; i++) if (e[i] > best) { best = e[i]; bi = i; }
    out[(size_t)NROWS * 35 + r]          = best * inv;            // pred_scores
    out[(size_t)NROWS * 35 + NROWS + r]  = (float)(bi + 1);       // pred_labels
}

// ---------------- pass3: human argmax per 64-row group ----------------
__global__ void k_pass3(float* __restrict__ out) {
    int g = blockIdx.x;
    int t = threadIdx.x;  // 64
    __shared__ float sv[64];
    __shared__ int   si[64];
    int r = g * PER + t;
    sv[t] = out[(size_t)r * 35 + 0];
    si[t] = t;
    __syncthreads();
    for (int off = 32; off > 0; off >>= 1) {
        if (t < off) {
            float v2 = sv[t + off]; int i2 = si[t + off];
            if (v2 > sv[t]) { sv[t] = v2; si[t] = i2; }  // tie keeps lower index (first max)
        }
        __syncthreads();
    }
    if (t == 0) {
        int h = g * PER + si[0];
        out[(size_t)NROWS * 35 + h]              = out[(size_t)h * 35 + 0];  // pred_scores[h]
        out[(size_t)NROWS * 35 + NROWS + h]      = 1.0f;                     // pred_labels[h]
        out[(size_t)NROWS * 35 + 2 * NROWS + g]  = (float)h;                 // human_idx
    }
}

// ---------------- launcher ----------------
extern "C" void kernel_launch(void* const* d_in, const int* in_sizes, int n_in,
                              void* d_out, int out_size) {
    const float* distribution = (const float*)d_in[0];
    const float* features     = (const float*)d_in[1];
    const float* boxes        = (const float*)d_in[2];
    const float* obj_embed_W  = (const float*)d_in[3];
    const float* bn4_g        = (const float*)d_in[4];
    const float* bn4_b        = (const float*)d_in[5];
    const float* bn4_m        = (const float*)d_in[6];
    const float* bn4_v        = (const float*)d_in[7];
    const float* pos_W        = (const float*)d_in[8];
    const float* pos_b        = (const float*)d_in[9];
    const float* dec1_W       = (const float*)d_in[10];
    const float* dec1_b       = (const float*)d_in[11];
    const float* bn1k_g       = (const float*)d_in[12];
    const float* bn1k_b       = (const float*)d_in[13];
    const float* bn1k_m       = (const float*)d_in[14];
    const float* bn1k_v       = (const float*)d_in[15];
    const float* dec2_W       = (const float*)d_in[16];
    const float* dec2_b       = (const float*)d_in[17];
    float* out = (float*)d_out;

    k_prep_a<<<(HID + 255) / 256, 256>>>(bn1k_g, bn1k_b, bn1k_m, bn1k_v, dec1_b);
    k_prep_pos<<<1, 128>>>(bn4_g, bn4_b, bn4_m, bn4_v, pos_W, pos_b);
    k_scale_w<<<(KP * HID + 255) / 256, 256>>>(dec1_W);
    k_m1<<<(35 * HID + 255) / 256, 256>>>(obj_embed_W, dec1_W);
    k_buildA<<<NROWS, 128>>>(features, distribution, boxes);
    k_gemm1<<<dim3(HID / BN, NROWS / BM), 256>>>();
    cudaFuncSetAttribute(k_pass2, cudaFuncAttributeMaxDynamicSharedMemorySize, HID * NC * 4);
    k_pass2<<<NROWS / 256, 256, HID * NC * 4>>>(dec2_W, dec2_b, out);
    k_pass3<<<NBLK, 64>>>(out);
}

// round 2
// speedup vs baseline: 1.0680x; 1.0680x over previous
#include <cuda_runtime.h>
#include <math.h>

#define NROWS 65536
#define PER   64
#define NBLK  1024
#define NC    36
#define OBJ   192
#define EMB   200
#define POSD  128
#define HID   1024
#define KEFF  355
#define KP    368
#define EPS   1e-5f

// ---------------- device scratch ----------------
__device__ float d_A[(size_t)NROWS * KP];     // fused input matrix [N, KP]
__device__ float d_W[(size_t)KP * HID];       // folded dec1 weights [KP, HID]
__device__ float d_b1[HID];
__device__ float d_a[HID];
__device__ float d_PW[4 * POSD];
__device__ float d_pb[POSD];
__device__ float d_g[(size_t)HID * NROWS];    // hidden activations TRANSPOSED [k][row]

// ---------------- prep kernels ----------------
__global__ void k_prep_a(const float* __restrict__ g, const float* __restrict__ b,
                         const float* __restrict__ m, const float* __restrict__ v,
                         const float* __restrict__ dec1_b) {
    int j = blockIdx.x * blockDim.x + threadIdx.x;
    if (j < HID) {
        float a = g[j] * rsqrtf(v[j] + EPS);
        float c = b[j] - m[j] * a;
        d_a[j]  = a;
        d_b1[j] = dec1_b[j] * a + c;
    }
}

__global__ void k_prep_pos(const float* __restrict__ g4, const float* __restrict__ b4,
                           const float* __restrict__ m4, const float* __restrict__ v4,
                           const float* __restrict__ pos_W, const float* __restrict__ pos_b) {
    int j = threadIdx.x;  // 128
    float s[4], t[4];
#pragma unroll
    for (int k = 0; k < 4; k++) {
        s[k] = g4[k] * rsqrtf(v4[k] + EPS);
        t[k] = b4[k] - m4[k] * s[k];
    }
    float pb = pos_b[j];
#pragma unroll
    for (int k = 0; k < 4; k++) {
        float w = pos_W[k * POSD + j];
        d_PW[k * POSD + j] = s[k] * w;
        pb += t[k] * w;
    }
    d_pb[j] = pb;
}

// scale dec1 weight columns; zero the obj_embed-folded region (filled by k_m1 atomics)
__global__ void k_scale_w(const float* __restrict__ dec1_W) {
    int idx = blockIdx.x * blockDim.x + threadIdx.x;
    if (idx >= KP * HID) return;
    int k = idx / HID, j = idx % HID;
    float v;
    if (k >= OBJ && k < OBJ + 35) v = 0.f;   // accumulated by k_m1
    else if (k < OBJ)       v = dec1_W[(size_t)k * HID + j] * d_a[j];
    else if (k < KEFF) v = dec1_W[(size_t)(OBJ + EMB + (k - (OBJ + 35))) * HID + j] * d_a[j];
    else               v = 0.f;
    d_W[idx] = v;
}

// M1 = obj_embed_W(35x200) @ dec1_W[192:392], k-split with atomic accumulation
__global__ void k_m1(const float* __restrict__ obj_embed_W, const float* __restrict__ dec1_W) {
    int j  = blockIdx.x * 256 + threadIdx.x;   // 4 blocks * 256 = 1024
    int e  = blockIdx.y;                        // 35
    int kc = blockIdx.z;                        // 4 chunks of 50
    float s = 0.f;
#pragma unroll 10
    for (int k = 0; k < 50; k++) {
        int kk = kc * 50 + k;
        s += obj_embed_W[e * EMB + kk] * dec1_W[(size_t)(OBJ + kk) * HID + j];
    }
    atomicAdd(&d_W[(size_t)(OBJ + e) * HID + j], s * d_a[j]);
}

// build fused A matrix per row: [features(192) | distribution(35) | pos(128) | pad(13)]
__global__ void k_buildA(const float* __restrict__ features,
                         const float* __restrict__ distribution,
                         const float* __restrict__ boxes) {
    int r = blockIdx.x;
    int j = threadIdx.x;  // 128
    float* Arow = &d_A[(size_t)r * KP];
    Arow[j] = features[(size_t)r * OBJ + j];
    if (j < 64) Arow[128 + j] = features[(size_t)r * OBJ + 128 + j];
    if (j < 35) Arow[OBJ + j] = distribution[(size_t)r * 35 + j];
    if (j >= 35 && j < 48) Arow[320 + j] = 0.f;  // pad cols 355..367

    float x1 = boxes[(size_t)r * 5 + 1], y1 = boxes[(size_t)r * 5 + 2];
    float x2 = boxes[(size_t)r * 5 + 3], y2 = boxes[(size_t)r * 5 + 4];
    float w = x2 - x1 + 1.f, h = y2 - y1 + 1.f;
    float c0 = x1 + 0.5f * w, c1 = y1 + 0.5f * h;
    float p = d_pb[j] + c0 * d_PW[j] + c1 * d_PW[POSD + j]
                     + w  * d_PW[2 * POSD + j] + h * d_PW[3 * POSD + j];
    Arow[OBJ + 35 + j] = fmaxf(p, 0.f);
}

// ---------------- GEMM1: 3xTF32 tensor-core, g^T = relu(A @ W + b1) ----------------
#define BM 128
#define BN 128
#define BK 16
#define NKB (KP / BK)   // 23
#define ASTRIDE 20      // BK + 4 pad -> conflict-free frag loads
#define BSTRIDE 136     // BN + 8 pad

__device__ __forceinline__ unsigned f2tf32(float x) {
    unsigned r;
    asm("cvt.rna.tf32.f32 %0, %1;" : "=r"(r) : "f"(x));
    return r;
}

__device__ __forceinline__ void mma_tf32(float& c0, float& c1, float& c2, float& c3,
                                         unsigned a0, unsigned a1, unsigned a2, unsigned a3,
                                         unsigned b0, unsigned b1) {
    asm volatile(
        "mma.sync.aligned.m16n8k8.row.col.f32.tf32.tf32.f32 "
        "{%0,%1,%2,%3}, {%4,%5,%6,%7}, {%8,%9}, {%0,%1,%2,%3};"
        : "+f"(c0), "+f"(c1), "+f"(c2), "+f"(c3)
        : "r"(a0), "r"(a1), "r"(a2), "r"(a3), "r"(b0), "r"(b1));
}

__global__ __launch_bounds__(256) void k_gemm1() {
    __shared__ float As[2][BM][ASTRIDE];   // [m][k]
    __shared__ float Bs[2][BK][BSTRIDE];   // [k][n]

    int t    = threadIdx.x;
    int lane = t & 31;
    int warp = t >> 5;
    int qr   = lane >> 2;   // 0..7
    int qc   = lane & 3;    // 0..3
    int wm   = (warp >> 2) * 64;   // warp row offset
    int wn   = (warp & 3) * 32;    // warp col offset
    int i0   = blockIdx.y * BM;
    int j0   = blockIdx.x * BN;

    // loader indices
    int ar = t >> 2;          // 0..63
    int ak = (t & 3) * 4;     // 0,4,8,12
    int br = t >> 4;          // 0..15
    int bc = (t & 15) * 8;    // 0..120

    float acc[4][4][4];
#pragma unroll
    for (int mi = 0; mi < 4; mi++)
#pragma unroll
        for (int ni = 0; ni < 4; ni++)
#pragma unroll
            for (int q = 0; q < 4; q++) acc[mi][ni][q] = 0.f;

    // prologue: tile 0 -> buf 0
    {
        float4 a0v = *(const float4*)&d_A[(size_t)(i0 + ar) * KP + ak];
        float4 a1v = *(const float4*)&d_A[(size_t)(i0 + 64 + ar) * KP + ak];
        const float* src = &d_W[(size_t)br * HID + j0 + bc];
        float4 b0v = *(const float4*)src;
        float4 b1v = *(const float4*)(src + 4);
        *(float4*)&As[0][ar][ak]      = a0v;
        *(float4*)&As[0][64 + ar][ak] = a1v;
        *(float4*)&Bs[0][br][bc]      = b0v;
        *(float4*)&Bs[0][br][bc + 4]  = b1v;
    }
    __syncthreads();

    for (int kb = 0; kb < NKB; kb++) {
        int cur = kb & 1, nxt = cur ^ 1;

        float4 pa0, pa1, pb0, pb1;
        if (kb < NKB - 1) {
            int k16 = (kb + 1) * BK;
            pa0 = *(const float4*)&d_A[(size_t)(i0 + ar) * KP + k16 + ak];
            pa1 = *(const float4*)&d_A[(size_t)(i0 + 64 + ar) * KP + k16 + ak];
            const float* src = &d_W[(size_t)(k16 + br) * HID + j0 + bc];
            pb0 = *(const float4*)src;
            pb1 = *(const float4*)(src + 4);
        }

#pragma unroll
        for (int ks = 0; ks < 2; ks++) {
            int k0 = ks * 8;
            // A fragments (hi/lo)
            unsigned ahi[4][4], alo[4][4];
#pragma unroll
            for (int mi = 0; mi < 4; mi++) {
                int m = wm + mi * 16 + qr;
                float x0 = As[cur][m][k0 + qc];
                float x1 = As[cur][m + 8][k0 + qc];
                float x2 = As[cur][m][k0 + qc + 4];
                float x3 = As[cur][m + 8][k0 + qc + 4];
                ahi[mi][0] = f2tf32(x0); alo[mi][0] = f2tf32(x0 - __uint_as_float(ahi[mi][0]));
                ahi[mi][1] = f2tf32(x1); alo[mi][1] = f2tf32(x1 - __uint_as_float(ahi[mi][1]));
                ahi[mi][2] = f2tf32(x2); alo[mi][2] = f2tf32(x2 - __uint_as_float(ahi[mi][2]));
                ahi[mi][3] = f2tf32(x3); alo[mi][3] = f2tf32(x3 - __uint_as_float(ahi[mi][3]));
            }
            // B fragments (hi/lo)
            unsigned bhi[4][2], blo[4][2];
#pragma unroll
            for (int ni = 0; ni < 4; ni++) {
                int n = wn + ni * 8 + qr;
                float y0 = Bs[cur][k0 + qc][n];
                float y1 = Bs[cur][k0 + qc + 4][n];
                bhi[ni][0] = f2tf32(y0); blo[ni][0] = f2tf32(y0 - __uint_as_float(bhi[ni][0]));
                bhi[ni][1] = f2tf32(y1); blo[ni][1] = f2tf32(y1 - __uint_as_float(bhi[ni][1]));
            }
            // three passes (independent accumulators back-to-back for pipelining)
#pragma unroll
            for (int mi = 0; mi < 4; mi++)
#pragma unroll
                for (int ni = 0; ni < 4; ni++)
                    mma_tf32(acc[mi][ni][0], acc[mi][ni][1], acc[mi][ni][2], acc[mi][ni][3],
                             ahi[mi][0], ahi[mi][1], ahi[mi][2], ahi[mi][3],
                             bhi[ni][0], bhi[ni][1]);
#pragma unroll
            for (int mi = 0; mi < 4; mi++)
#pragma unroll
                for (int ni = 0; ni < 4; ni++)
                    mma_tf32(acc[mi][ni][0], acc[mi][ni][1], acc[mi][ni][2], acc[mi][ni][3],
                             alo[mi][0], alo[mi][1], alo[mi][2], alo[mi][3],
                             bhi[ni][0], bhi[ni][1]);
#pragma unroll
            for (int mi = 0; mi < 4; mi++)
#pragma unroll
                for (int ni = 0; ni < 4; ni++)
                    mma_tf32(acc[mi][ni][0], acc[mi][ni][1], acc[mi][ni][2], acc[mi][ni][3],
                             ahi[mi][0], ahi[mi][1], ahi[mi][2], ahi[mi][3],
                             blo[ni][0], blo[ni][1]);
        }

        if (kb < NKB - 1) {
            *(float4*)&As[nxt][ar][ak]      = pa0;
            *(float4*)&As[nxt][64 + ar][ak] = pa1;
            *(float4*)&Bs[nxt][br][bc]      = pb0;
            *(float4*)&Bs[nxt][br][bc + 4]  = pb1;
        }
        __syncthreads();
    }

    // epilogue: bias + relu, transposed stores (per (j, half-tile): 8 lanes cover
    // 8 consecutive rows -> full 32B sectors)
#pragma unroll
    for (int mi = 0; mi < 4; mi++) {
        int r = i0 + wm + mi * 16 + qr;
#pragma unroll
        for (int ni = 0; ni < 4; ni++) {
            int j = j0 + wn + ni * 8 + 2 * qc;
            float bj0 = d_b1[j], bj1 = d_b1[j + 1];
            float* g0 = &d_g[(size_t)j * NROWS];
            float* g1 = &d_g[(size_t)(j + 1) * NROWS];
            g0[r]     = fmaxf(acc[mi][ni][0] + bj0, 0.f);
            g1[r]     = fmaxf(acc[mi][ni][1] + bj1, 0.f);
            g0[r + 8] = fmaxf(acc[mi][ni][2] + bj0, 0.f);
            g1[r + 8] = fmaxf(acc[mi][ni][3] + bj1, 0.f);
        }
    }
}

// ---------------- pass2: logits + softmax + pred ----------------
__global__ __launch_bounds__(256) void k_pass2(const float* __restrict__ dec2_W,
                                               const float* __restrict__ dec2_b,
                                               float* __restrict__ out) {
    extern __shared__ float Ws[];  // 1024*36
    int t = threadIdx.x;
    for (int i = t; i < HID * NC / 4; i += 256)
        ((float4*)Ws)[i] = ((const float4*)dec2_W)[i];
    __syncthreads();

    int r = blockIdx.x * 256 + t;
    float acc[NC];
#pragma unroll
    for (int c = 0; c < NC; c++) acc[c] = dec2_b[c];

#pragma unroll 4
    for (int k = 0; k < HID; k++) {
        float v = d_g[(size_t)k * NROWS + r];
        const float4* wr = (const float4*)&Ws[k * NC];
#pragma unroll
        for (int c4 = 0; c4 < NC / 4; c4++) {
            float4 w = wr[c4];
            acc[c4 * 4 + 0] += v * w.x;
            acc[c4 * 4 + 1] += v * w.y;
            acc[c4 * 4 + 2] += v * w.z;
            acc[c4 * 4 + 3] += v * w.w;
        }
    }

    float m = acc[1];
#pragma unroll
    for (int c = 2; c < NC; c++) m = fmaxf(m, acc[c]);
    float e[35], s = 0.f;
#pragma unroll
    for (int i = 0; i < 35; i++) { e[i] = expf(acc[1 + i] - m); s += e[i]; }
    float inv = 1.f / s;
#pragma unroll
    for (int i = 0; i < 35; i++) out[(size_t)r * 35 + i] = e[i] * inv;

    float best = e[1]; int bi = 1;
#pragma unroll
    for (int i = 2; i < 35; i++) if (e[i] > best) { best = e[i]; bi = i; }
    out[(size_t)NROWS * 35 + r]         = best * inv;        // pred_scores
    out[(size_t)NROWS * 35 + NROWS + r] = (float)(bi + 1);   // pred_labels
}

// ---------------- pass3: human argmax per 64-row group ----------------
__global__ void k_pass3(float* __restrict__ out) {
    int g = blockIdx.x;
    int t = threadIdx.x;  // 64
    __shared__ float sv[64];
    __shared__ int   si[64];
    int r = g * PER + t;
    sv[t] = out[(size_t)r * 35 + 0];
    si[t] = t;
    __syncthreads();
    for (int off = 32; off > 0; off >>= 1) {
        if (t < off) {
            float v2 = sv[t + off]; int i2 = si[t + off];
            if (v2 > sv[t]) { sv[t] = v2; si[t] = i2; }
        }
        __syncthreads();
    }
    if (t == 0) {
        int h = g * PER + si[0];
        out[(size_t)NROWS * 35 + h]             = out[(size_t)h * 35 + 0];
        out[(size_t)NROWS * 35 + NROWS + h]     = 1.0f;
        out[(size_t)NROWS * 35 + 2 * NROWS + g] = (float)h;
    }
}

// ---------------- launcher ----------------
extern "C" void kernel_launch(void* const* d_in, const int* in_sizes, int n_in,
                              void* d_out, int out_size) {
    const float* distribution = (const float*)d_in[0];
    const float* features     = (const float*)d_in[1];
    const float* boxes        = (const float*)d_in[2];
    const float* obj_embed_W  = (const float*)d_in[3];
    const float* bn4_g        = (const float*)d_in[4];
    const float* bn4_b        = (const float*)d_in[5];
    const float* bn4_m        = (const float*)d_in[6];
    const float* bn4_v        = (const float*)d_in[7];
    const float* pos_W        = (const float*)d_in[8];
    const float* pos_b        = (const float*)d_in[9];
    const float* dec1_W       = (const float*)d_in[10];
    const float* dec1_b       = (const float*)d_in[11];
    const float* bn1k_g       = (const float*)d_in[12];
    const float* bn1k_b       = (const float*)d_in[13];
    const float* bn1k_m       = (const float*)d_in[14];
    const float* bn1k_v       = (const float*)d_in[15];
    const float* dec2_W       = (const float*)d_in[16];
    const float* dec2_b       = (const float*)d_in[17];
    float* out = (float*)d_out;

    k_prep_a<<<(HID + 255) / 256, 256>>>(bn1k_g, bn1k_b, bn1k_m, bn1k_v, dec1_b);
    k_prep_pos<<<1, 128>>>(bn4_g, bn4_b, bn4_m, bn4_v, pos_W, pos_b);
    k_scale_w<<<(KP * HID + 255) / 256, 256>>>(dec1_W);
    k_m1<<<dim3(4, 35, 4), 256>>>(obj_embed_W, dec1_W);
    k_buildA<<<NROWS, 128>>>(features, distribution, boxes);
    k_gemm1<<<dim3(HID / BN, NROWS / BM), 256>>>();
    cudaFuncSetAttribute(k_pass2, cudaFuncAttributeMaxDynamicSharedMemorySize, HID * NC * 4);
    k_pass2<<<NROWS / 256, 256, HID * NC * 4>>>(dec2_W, dec2_b, out);
    k_pass3<<<NBLK, 64>>>(out);
}

// round 4
// speedup vs baseline: 1.1281x; 1.0562x over previous
#include <cuda_runtime.h>
#include <math.h>
#include <stdint.h>

#define NROWS 65536
#define PER   64
#define NBLK  1024
#define NC    36
#define OBJ   192
#define EMB   200
#define POSD  128
#define HID   1024
#define KEFF  355
#define KP    368
#define EPS   1e-5f

// ---------------- device scratch ----------------
__device__ float d_Ah[(size_t)NROWS * KP];    // A hi (tf32-rounded)
__device__ float d_Al[(size_t)NROWS * KP];    // A lo (tf32-rounded residual)
__device__ float d_W [(size_t)KP * HID];      // folded dec1 weights (fp32)
__device__ float d_Wh[(size_t)KP * HID];      // W hi
__device__ float d_Wl[(size_t)KP * HID];      // W lo
__device__ float d_m1p[4][35 * HID];          // k_m1 partial sums (deterministic reduce)
__device__ float d_b1[HID];
__device__ float d_a[HID];
__device__ float d_PW[4 * POSD];
__device__ float d_pb[POSD];
__device__ float d_g[(size_t)HID * NROWS];    // hidden activations TRANSPOSED [k][row]

__device__ __forceinline__ unsigned f2tf32(float x) {
    unsigned r;
    asm("cvt.rna.tf32.f32 %0, %1;" : "=r"(r) : "f"(x));
    return r;
}

// ---------------- prep kernels ----------------
__global__ void k_prep_a(const float* __restrict__ g, const float* __restrict__ b,
                         const float* __restrict__ m, const float* __restrict__ v,
                         const float* __restrict__ dec1_b) {
    int j = blockIdx.x * blockDim.x + threadIdx.x;
    if (j < HID) {
        float a = g[j] * rsqrtf(v[j] + EPS);
        float c = b[j] - m[j] * a;
        d_a[j]  = a;
        d_b1[j] = dec1_b[j] * a + c;
    }
}

__global__ void k_prep_pos(const float* __restrict__ g4, const float* __restrict__ b4,
                           const float* __restrict__ m4, const float* __restrict__ v4,
                           const float* __restrict__ pos_W, const float* __restrict__ pos_b) {
    int j = threadIdx.x;  // 128
    float s[4], t[4];
#pragma unroll
    for (int k = 0; k < 4; k++) {
        s[k] = g4[k] * rsqrtf(v4[k] + EPS);
        t[k] = b4[k] - m4[k] * s[k];
    }
    float pb = pos_b[j];
#pragma unroll
    for (int k = 0; k < 4; k++) {
        float w = pos_W[k * POSD + j];
        d_PW[k * POSD + j] = s[k] * w;
        pb += t[k] * w;
    }
    d_pb[j] = pb;
}

// scale dec1 weight columns (obj_embed-folded region filled by k_m1sum)
__global__ void k_scale_w(const float* __restrict__ dec1_W) {
    int idx = blockIdx.x * blockDim.x + threadIdx.x;
    if (idx >= KP * HID) return;
    int k = idx / HID, j = idx % HID;
    if (k >= OBJ && k < OBJ + 35) return;   // written by k_m1sum
    float v;
    if (k < OBJ)       v = dec1_W[(size_t)k * HID + j] * d_a[j];
    else if (k < KEFF) v = dec1_W[(size_t)(OBJ + EMB + (k - (OBJ + 35))) * HID + j] * d_a[j];
    else               v = 0.f;
    d_W[idx] = v;
}

// M1 partials: obj_embed_W(35x200) @ dec1_W[192:392], k-split, NO atomics
__global__ void k_m1(const float* __restrict__ obj_embed_W, const float* __restrict__ dec1_W) {
    int j  = blockIdx.x * 256 + threadIdx.x;   // 4 * 256 = 1024
    int e  = blockIdx.y;                        // 35
    int kc = blockIdx.z;                        // 4 chunks of 50
    float s = 0.f;
#pragma unroll 10
    for (int k = 0; k < 50; k++) {
        int kk = kc * 50 + k;
        s += obj_embed_W[e * EMB + kk] * dec1_W[(size_t)(OBJ + kk) * HID + j];
    }
    d_m1p[kc][e * HID + j] = s;
}

// deterministic fixed-order combine of the 4 partials
__global__ void k_m1sum() {
    int idx = blockIdx.x * 256 + threadIdx.x;  // 35 * 1024
    if (idx >= 35 * HID) return;
    int j = idx % HID;
    float s = ((d_m1p[0][idx] + d_m1p[1][idx]) + d_m1p[2][idx]) + d_m1p[3][idx];
    d_W[(size_t)OBJ * HID + idx] = s * d_a[j];
}

// split folded W into tf32 hi/lo
__global__ void k_split_w() {
    int idx = blockIdx.x * blockDim.x + threadIdx.x;
    if (idx >= KP * HID) return;
    float v = d_W[idx];
    unsigned h = f2tf32(v);
    d_Wh[idx] = __uint_as_float(h);
    d_Wl[idx] = __uint_as_float(f2tf32(v - __uint_as_float(h)));
}

// build fused A (pre-split hi/lo): [features(192) | distribution(35) | pos(128) | pad(13)]
__global__ void k_buildA(const float* __restrict__ features,
                         const float* __restrict__ distribution,
                         const float* __restrict__ boxes) {
    int r = blockIdx.x;
    int j = threadIdx.x;  // 128
    size_t base = (size_t)r * KP;
    auto put = [&](int col, float v) {
        unsigned h = f2tf32(v);
        d_Ah[base + col] = __uint_as_float(h);
        d_Al[base + col] = __uint_as_float(f2tf32(v - __uint_as_float(h)));
    };
    put(j, features[(size_t)r * OBJ + j]);
    if (j < 64) put(128 + j, features[(size_t)r * OBJ + 128 + j]);
    if (j < 35) put(OBJ + j, distribution[(size_t)r * 35 + j]);
    if (j >= 35 && j < 48) { d_Ah[base + 320 + j] = 0.f; d_Al[base + 320 + j] = 0.f; }

    float x1 = boxes[(size_t)r * 5 + 1], y1 = boxes[(size_t)r * 5 + 2];
    float x2 = boxes[(size_t)r * 5 + 3], y2 = boxes[(size_t)r * 5 + 4];
    float w = x2 - x1 + 1.f, h = y2 - y1 + 1.f;
    float c0 = x1 + 0.5f * w, c1 = y1 + 0.5f * h;
    float p = d_pb[j] + c0 * d_PW[j] + c1 * d_PW[POSD + j]
                     + w  * d_PW[2 * POSD + j] + h * d_PW[3 * POSD + j];
    put(OBJ + 35 + j, fmaxf(p, 0.f));
}

// ---------------- GEMM1: 3xTF32 tensor-core, cp.async pipeline ----------------
#define BM 128
#define BN 128
#define BK 16
#define NKB (KP / BK)   // 23
#define ASTRIDE 20
#define BSTRIDE 136
#define A_TILE (BM * ASTRIDE)
#define B_TILE (BK * BSTRIDE)

__device__ __forceinline__ void mma_tf32(float& c0, float& c1, float& c2, float& c3,
                                         unsigned a0, unsigned a1, unsigned a2, unsigned a3,
                                         unsigned b0, unsigned b1) {
    asm volatile(
        "mma.sync.aligned.m16n8k8.row.col.f32.tf32.tf32.f32 "
        "{%0,%1,%2,%3}, {%4,%5,%6,%7}, {%8,%9}, {%0,%1,%2,%3};"
        : "+f"(c0), "+f"(c1), "+f"(c2), "+f"(c3)
        : "r"(a0), "r"(a1), "r"(a2), "r"(a3), "r"(b0), "r"(b1));
}

__device__ __forceinline__ void cp16(uint32_t dst, const float* src) {
    asm volatile("cp.async.ca.shared.global [%0], [%1], 16;" :: "r"(dst), "l"(src));
}

__global__ __launch_bounds__(256) void k_gemm1() {
    extern __shared__ float sm[];
    float* sAh = sm;
    float* sAl = sAh + 2 * A_TILE;
    float* sBh = sAl + 2 * A_TILE;
    float* sBl = sBh + 2 * B_TILE;

    int t    = threadIdx.x;
    int lane = t & 31;
    int warp = t >> 5;
    int qr   = lane >> 2;
    int qc   = lane & 3;
    int wm   = (warp >> 2) * 64;
    int wn   = (warp & 3) * 32;
    int i0   = blockIdx.y * BM;
    int j0   = blockIdx.x * BN;

    int ar = t >> 2;
    int ak = (t & 3) * 4;
    int br = t >> 4;
    int bc = (t & 15) * 8;

    uint32_t uAh = (uint32_t)__cvta_generic_to_shared(sAh);
    uint32_t uAl = (uint32_t)__cvta_generic_to_shared(sAl);
    uint32_t uBh = (uint32_t)__cvta_generic_to_shared(sBh);
    uint32_t uBl = (uint32_t)__cvta_generic_to_shared(sBl);

    float acc[4][4][4];
#pragma unroll
    for (int mi = 0; mi < 4; mi++)
#pragma unroll
        for (int ni = 0; ni < 4; ni++)
#pragma unroll
            for (int q = 0; q < 4; q++) acc[mi][ni][q] = 0.f;

    auto load_stage = [&](int buf, int kb) {
        int k16 = kb * BK;
        uint32_t a_off0 = uAh + ((buf * BM + ar) * ASTRIDE + ak) * 4;
        uint32_t a_off1 = uAh + ((buf * BM + 64 + ar) * ASTRIDE + ak) * 4;
        cp16(a_off0, &d_Ah[(size_t)(i0 + ar) * KP + k16 + ak]);
        cp16(a_off1, &d_Ah[(size_t)(i0 + 64 + ar) * KP + k16 + ak]);
        cp16(a_off0 + (uAl - uAh), &d_Al[(size_t)(i0 + ar) * KP + k16 + ak]);
        cp16(a_off1 + (uAl - uAh), &d_Al[(size_t)(i0 + 64 + ar) * KP + k16 + ak]);
        uint32_t b_off = uBh + ((buf * BK + br) * BSTRIDE + bc) * 4;
        size_t   gBi   = (size_t)(k16 + br) * HID + j0 + bc;
        cp16(b_off,      &d_Wh[gBi]);
        cp16(b_off + 16, &d_Wh[gBi + 4]);
        cp16(b_off + (uBl - uBh),      &d_Wl[gBi]);
        cp16(b_off + (uBl - uBh) + 16, &d_Wl[gBi + 4]);
    };

    load_stage(0, 0);
    asm volatile("cp.async.commit_group;");

    for (int kb = 0; kb < NKB; kb++) {
        int cur = kb & 1;
        if (kb + 1 < NKB) {
            load_stage(cur ^ 1, kb + 1);
            asm volatile("cp.async.commit_group;");
            asm volatile("cp.async.wait_group 1;");
        } else {
            asm volatile("cp.async.wait_group 0;");
        }
        __syncthreads();

        const float* Ahb = sAh + cur * A_TILE;
        const float* Alb = sAl + cur * A_TILE;
        const float* Bhb = sBh + cur * B_TILE;
        const float* Blb = sBl + cur * B_TILE;

#pragma unroll
        for (int ks = 0; ks < 2; ks++) {
            int k0 = ks * 8;
            unsigned ahi[4][4], alo[4][4];
#pragma unroll
            for (int mi = 0; mi < 4; mi++) {
                int m = wm + mi * 16 + qr;
                ahi[mi][0] = __float_as_uint(Ahb[m * ASTRIDE + k0 + qc]);
                ahi[mi][1] = __float_as_uint(Ahb[(m + 8) * ASTRIDE + k0 + qc]);
                ahi[mi][2] = __float_as_uint(Ahb[m * ASTRIDE + k0 + qc + 4]);
                ahi[mi][3] = __float_as_uint(Ahb[(m + 8) * ASTRIDE + k0 + qc + 4]);
                alo[mi][0] = __float_as_uint(Alb[m * ASTRIDE + k0 + qc]);
                alo[mi][1] = __float_as_uint(Alb[(m + 8) * ASTRIDE + k0 + qc]);
                alo[mi][2] = __float_as_uint(Alb[m * ASTRIDE + k0 + qc + 4]);
                alo[mi][3] = __float_as_uint(Alb[(m + 8) * ASTRIDE + k0 + qc + 4]);
            }
            unsigned bhi[4][2], blo[4][2];
#pragma unroll
            for (int ni = 0; ni < 4; ni++) {
                int n = wn + ni * 8 + qr;
                bhi[ni][0] = __float_as_uint(Bhb[(k0 + qc) * BSTRIDE + n]);
                bhi[ni][1] = __float_as_uint(Bhb[(k0 + qc + 4) * BSTRIDE + n]);
                blo[ni][0] = __float_as_uint(Blb[(k0 + qc) * BSTRIDE + n]);
                blo[ni][1] = __float_as_uint(Blb[(k0 + qc + 4) * BSTRIDE + n]);
            }
#pragma unroll
            for (int mi = 0; mi < 4; mi++)
#pragma unroll
                for (int ni = 0; ni < 4; ni++)
                    mma_tf32(acc[mi][ni][0], acc[mi][ni][1], acc[mi][ni][2], acc[mi][ni][3],
                             ahi[mi][0], ahi[mi][1], ahi[mi][2], ahi[mi][3],
                             bhi[ni][0], bhi[ni][1]);
#pragma unroll
            for (int mi = 0; mi < 4; mi++)
#pragma unroll
                for (int ni = 0; ni < 4; ni++)
                    mma_tf32(acc[mi][ni][0], acc[mi][ni][1], acc[mi][ni][2], acc[mi][ni][3],
                             alo[mi][0], alo[mi][1], alo[mi][2], alo[mi][3],
                             bhi[ni][0], bhi[ni][1]);
#pragma unroll
            for (int mi = 0; mi < 4; mi++)
#pragma unroll
                for (int ni = 0; ni < 4; ni++)
                    mma_tf32(acc[mi][ni][0], acc[mi][ni][1], acc[mi][ni][2], acc[mi][ni][3],
                             ahi[mi][0], ahi[mi][1], ahi[mi][2], ahi[mi][3],
                             blo[ni][0], blo[ni][1]);
        }
        __syncthreads();
    }

    // epilogue: bias + relu, transposed stores
#pragma unroll
    for (int mi = 0; mi < 4; mi++) {
        int r = i0 + wm + mi * 16 + qr;
#pragma unroll
        for (int ni = 0; ni < 4; ni++) {
            int j = j0 + wn + ni * 8 + 2 * qc;
            float bj0 = d_b1[j], bj1 = d_b1[j + 1];
            float* g0 = &d_g[(size_t)j * NROWS];
            float* g1 = &d_g[(size_t)(j + 1) * NROWS];
            g0[r]     = fmaxf(acc[mi][ni][0] + bj0, 0.f);
            g1[r]     = fmaxf(acc[mi][ni][1] + bj1, 0.f);
            g0[r + 8] = fmaxf(acc[mi][ni][2] + bj0, 0.f);
            g1[r + 8] = fmaxf(acc[mi][ni][3] + bj1, 0.f);
        }
    }
}

// ---------------- pass2: logits + softmax + pred ----------------
__global__ __launch_bounds__(256) void k_pass2(const float* __restrict__ dec2_W,
                                               const float* __restrict__ dec2_b,
                                               float* __restrict__ out) {
    extern __shared__ float Ws[];
    int t = threadIdx.x;
    for (int i = t; i < HID * NC / 4; i += 256)
        ((float4*)Ws)[i] = ((const float4*)dec2_W)[i];
    __syncthreads();

    int r = blockIdx.x * 256 + t;
    float acc[NC];
#pragma unroll
    for (int c = 0; c < NC; c++) acc[c] = dec2_b[c];

#pragma unroll 4
    for (int k = 0; k < HID; k++) {
        float v = d_g[(size_t)k * NROWS + r];
        const float4* wr = (const float4*)&Ws[k * NC];
#pragma unroll
        for (int c4 = 0; c4 < NC / 4; c4++) {
            float4 w = wr[c4];
            acc[c4 * 4 + 0] += v * w.x;
            acc[c4 * 4 + 1] += v * w.y;
            acc[c4 * 4 + 2] += v * w.z;
            acc[c4 * 4 + 3] += v * w.w;
        }
    }

    float m = acc[1];
#pragma unroll
    for (int c = 2; c < NC; c++) m = fmaxf(m, acc[c]);
    float e[35], s = 0.f;
#pragma unroll
    for (int i = 0; i < 35; i++) { e[i] = expf(acc[1 + i] - m); s += e[i]; }
    float inv = 1.f / s;
#pragma unroll
    for (int i = 0; i < 35; i++) out[(size_t)r * 35 + i] = e[i] * inv;

    float best = e[1]; int bi = 1;
#pragma unroll
    for (int i = 2; i < 35; i++) if (e[i] > best) { best = e[i]; bi = i; }
    out[(size_t)NROWS * 35 + r]         = best * inv;
    out[(size_t)NROWS * 35 + NROWS + r] = (float)(bi + 1);
}

// ---------------- pass3: human argmax per 64-row group ----------------
__global__ void k_pass3(float* __restrict__ out) {
    int g = blockIdx.x;
    int t = threadIdx.x;  // 64
    __shared__ float sv[64];
    __shared__ int   si[64];
    int r = g * PER + t;
    sv[t] = out[(size_t)r * 35 + 0];
    si[t] = t;
    __syncthreads();
    for (int off = 32; off > 0; off >>= 1) {
        if (t < off) {
            float v2 = sv[t + off]; int i2 = si[t + off];
            if (v2 > sv[t]) { sv[t] = v2; si[t] = i2; }
        }
        __syncthreads();
    }
    if (t == 0) {
        int h = g * PER + si[0];
        out[(size_t)NROWS * 35 + h]             = out[(size_t)h * 35 + 0];
        out[(size_t)NROWS * 35 + NROWS + h]     = 1.0f;
        out[(size_t)NROWS * 35 + 2 * NROWS + g] = (float)h;
    }
}

// ---------------- launcher ----------------
extern "C" void kernel_launch(void* const* d_in, const int* in_sizes, int n_in,
                              void* d_out, int out_size) {
    const float* distribution = (const float*)d_in[0];
    const float* features     = (const float*)d_in[1];
    const float* boxes        = (const float*)d_in[2];
    const float* obj_embed_W  = (const float*)d_in[3];
    const float* bn4_g        = (const float*)d_in[4];
    const float* bn4_b        = (const float*)d_in[5];
    const float* bn4_m        = (const float*)d_in[6];
    const float* bn4_v        = (const float*)d_in[7];
    const float* pos_W        = (const float*)d_in[8];
    const float* pos_b        = (const float*)d_in[9];
    const float* dec1_W       = (const float*)d_in[10];
    const float* dec1_b       = (const float*)d_in[11];
    const float* bn1k_g       = (const float*)d_in[12];
    const float* bn1k_b       = (const float*)d_in[13];
    const float* bn1k_m       = (const float*)d_in[14];
    const float* bn1k_v       = (const float*)d_in[15];
    const float* dec2_W       = (const float*)d_in[16];
    const float* dec2_b       = (const float*)d_in[17];
    float* out = (float*)d_out;

    k_prep_a<<<(HID + 255) / 256, 256>>>(bn1k_g, bn1k_b, bn1k_m, bn1k_v, dec1_b);
    k_prep_pos<<<1, 128>>>(bn4_g, bn4_b, bn4_m, bn4_v, pos_W, pos_b);
    k_scale_w<<<(KP * HID + 255) / 256, 256>>>(dec1_W);
    k_m1<<<dim3(4, 35, 4), 256>>>(obj_embed_W, dec1_W);
    k_m1sum<<<(35 * HID + 255) / 256, 256>>>();
    k_split_w<<<(KP * HID + 255) / 256, 256>>>();
    k_buildA<<<NROWS, 128>>>(features, distribution, boxes);

    int smem_gemm = (2 * A_TILE * 2 + 2 * B_TILE * 2) * 4;  // 75776 bytes
    cudaFuncSetAttribute(k_gemm1, cudaFuncAttributeMaxDynamicSharedMemorySize, smem_gemm);
    k_gemm1<<<dim3(HID / BN, NROWS / BM), 256, smem_gemm>>>();

    cudaFuncSetAttribute(k_pass2, cudaFuncAttributeMaxDynamicSharedMemorySize, HID * NC * 4);
    k_pass2<<<NROWS / 256, 256, HID * NC * 4>>>(dec2_W, dec2_b, out);
    k_pass3<<<NBLK, 64>>>(out);
}

// round 8
// speedup vs baseline: 1.5519x; 1.3757x over previous
#include <cuda_runtime.h>
#include <cuda_fp16.h>
#include <math.h>
#include <stdint.h>

#define NROWS 65536
#define PER   64
#define NBLK  1024
#define NC    36
#define OBJ   192
#define EMB   200
#define POSD  128
#define HID   1024
#define KEFF  355
#define KP    384          // 12 chunks of 32
#define EPS   1e-5f

#define WSCALE    64.f     // keep fp16 residuals of W in normal range
#define INV_WSCALE 0.015625f

// GEMM1 tiling (legacy mma.sync m16n8k16 fp16, 3-pass compensated)
#define BM 128
#define BN 128
#define BKC 32
#define NCH (KP / BKC)            // 12
#define SASTRIDE 40               // halfs per SMEM row (80B rows, 16B-aligned)
#define SWSTRIDE (SASTRIDE / 2)   // 20 words per row
#define TILE_HALFS (128 * SASTRIDE)
#define TILE_BYTES (TILE_HALFS * 2)      // 10240
#define STAGE_BYTES (4 * TILE_BYTES)     // Ah, Al, Bh, Bl = 40960
#define SMEM_GEMM (2 * STAGE_BYTES)      // 81920

// ---------------- device scratch ----------------
__device__ __half d_Ah[(size_t)NROWS * KP];   // A hi (fp16)
__device__ __half d_Al[(size_t)NROWS * KP];   // A lo (fp16 residual)
__device__ __half d_WhT[(size_t)HID * KP];    // folded W*64 hi, transposed [j][k]
__device__ __half d_WlT[(size_t)HID * KP];    // folded W*64 lo, transposed [j][k]
__device__ float  d_b1[HID];
__device__ float  d_a[HID];
__device__ float  d_PW[4 * POSD];
__device__ float  d_pb[POSD];
__device__ float  d_g[(size_t)HID * NROWS];   // hidden activations TRANSPOSED [j][row]

// ---------------- launch 1: fused prep (bn folds) ----------------
__global__ void k_prep(const float* __restrict__ bn1k_g, const float* __restrict__ bn1k_b,
                       const float* __restrict__ bn1k_m, const float* __restrict__ bn1k_v,
                       const float* __restrict__ dec1_b,
                       const float* __restrict__ g4, const float* __restrict__ b4,
                       const float* __restrict__ m4, const float* __restrict__ v4,
                       const float* __restrict__ pos_W, const float* __restrict__ pos_b) {
    int b = blockIdx.x, t = threadIdx.x;
    if (b < 4) {                       // bn1k fold: 4 blocks x 256 = 1024
        int j = b * 256 + t;
        float a = bn1k_g[j] * rsqrtf(bn1k_v[j] + EPS);
        float c = bn1k_b[j] - bn1k_m[j] * a;
        d_a[j]  = a;
        d_b1[j] = dec1_b[j] * a + c;
    } else if (t < POSD) {             // bn4 + pos fold
        int j = t;
        float s[4], tt[4];
#pragma unroll
        for (int k = 0; k < 4; k++) {
            s[k]  = g4[k] * rsqrtf(v4[k] + EPS);
            tt[k] = b4[k] - m4[k] * s[k];
        }
        float pb = pos_b[j];
#pragma unroll
        for (int k = 0; k < 4; k++) {
            float w = pos_W[k * POSD + j];
            d_PW[k * POSD + j] = s[k] * w;
            pb += tt[k] * w;
        }
        d_pb[j] = pb;
    }
}

// ---------------- launch 2: fold W (incl. obj_embed GEMM), scale, split fp16 ----------------
__global__ void k_weights(const float* __restrict__ dec1_W,
                          const float* __restrict__ obj_embed_W) {
    int idx = blockIdx.x * 256 + threadIdx.x;   // over [j][k], HID*KP
    if (idx >= HID * KP) return;
    int j = idx / KP, k = idx % KP;
    float v;
    if (k < OBJ) {
        v = dec1_W[(size_t)k * HID + j];
    } else if (k < OBJ + 35) {
        int e = k - OBJ;
        const float* er = obj_embed_W + e * EMB;
        float s = 0.f;
#pragma unroll 8
        for (int kk = 0; kk < EMB; kk++)
            s += er[kk] * dec1_W[(size_t)(OBJ + kk) * HID + j];
        v = s;
    } else if (k < KEFF) {
        v = dec1_W[(size_t)(OBJ + EMB + (k - (OBJ + 35))) * HID + j];
    } else {
        v = 0.f;
    }
    v *= d_a[j] * WSCALE;              // scale so fp16 residual stays normal-range
    __half h = __float2half_rn(v);
    d_WhT[idx] = h;
    d_WlT[idx] = __float2half_rn(v - __half2float(h));
}

// ---------------- launch 3: build fused A, pre-split fp16 ----------------
// layout: [features(192) | distribution(35) | pos(128) | pad(29)]
__global__ void k_buildA(const float* __restrict__ features,
                         const float* __restrict__ distribution,
                         const float* __restrict__ boxes) {
    int r = blockIdx.x;
    int j = threadIdx.x;  // 128
    size_t base = (size_t)r * KP;
    auto put = [&](int col, float v) {
        __half h = __float2half_rn(v);
        d_Ah[base + col] = h;
        d_Al[base + col] = __float2half_rn(v - __half2float(h));
    };
    put(j, features[(size_t)r * OBJ + j]);
    if (j < 64) put(128 + j, features[(size_t)r * OBJ + 128 + j]);
    if (j < 35) put(OBJ + j, distribution[(size_t)r * 35 + j]);
    if (j >= 35 && j < 64) {                        // pad cols 355..383
        d_Ah[base + 320 + j] = __float2half_rn(0.f);
        d_Al[base + 320 + j] = __float2half_rn(0.f);
    }
    float x1 = boxes[(size_t)r * 5 + 1], y1 = boxes[(size_t)r * 5 + 2];
    float x2 = boxes[(size_t)r * 5 + 3], y2 = boxes[(size_t)r * 5 + 4];
    float w = x2 - x1 + 1.f, h = y2 - y1 + 1.f;
    float c0 = x1 + 0.5f * w, c1 = y1 + 0.5f * h;
    float p = d_pb[j] + c0 * d_PW[j] + c1 * d_PW[POSD + j]
                     + w  * d_PW[2 * POSD + j] + h * d_PW[3 * POSD + j];
    put(OBJ + 35 + j, fmaxf(p, 0.f));
}

// ---------------- launch 4: GEMM1, fp16x3 legacy tensor, g^T = relu(A @ W + b1) ----------------
__device__ __forceinline__ void mma_f16(float& c0, float& c1, float& c2, float& c3,
                                        uint32_t a0, uint32_t a1, uint32_t a2, uint32_t a3,
                                        uint32_t b0, uint32_t b1) {
    asm volatile(
        "mma.sync.aligned.m16n8k16.row.col.f32.f16.f16.f32 "
        "{%0,%1,%2,%3}, {%4,%5,%6,%7}, {%8,%9}, {%0,%1,%2,%3};"
        : "+f"(c0), "+f"(c1), "+f"(c2), "+f"(c3)
        : "r"(a0), "r"(a1), "r"(a2), "r"(a3), "r"(b0), "r"(b1));
}
__device__ __forceinline__ void cp16(uint32_t dst, const void* src) {
    asm volatile("cp.async.ca.shared.global [%0], [%1], 16;" :: "r"(dst), "l"(src));
}

__global__ __launch_bounds__(256, 2) void k_gemm1() {
    extern __shared__ __half sh[];
    uint32_t su = (uint32_t)__cvta_generic_to_shared(sh);

    int t    = threadIdx.x;
    int lane = t & 31;
    int warp = t >> 5;
    int qr   = lane >> 2;          // 0..7
    int qc   = lane & 3;           // 0..3
    int wm   = (warp >> 2) * 64;   // 2 warp-rows
    int wn   = (warp & 3) * 32;    // 4 warp-cols
    int i0   = blockIdx.y * BM;
    int j0   = blockIdx.x * BN;

    float acc[4][4][4];
#pragma unroll
    for (int mi = 0; mi < 4; mi++)
#pragma unroll
        for (int ni = 0; ni < 4; ni++)
#pragma unroll
            for (int q = 0; q < 4; q++) acc[mi][ni][q] = 0.f;

    // stage loader: 8 cp16 per thread (Ah, Al, Bh, Bl tiles 128x32 fp16, 80B rows)
    auto load_stage = [&](int buf, int c) {
        int k0 = c * BKC;
        uint32_t base = su + buf * STAGE_BYTES;
#pragma unroll
        for (int q = 0; q < 2; q++) {
            int idx = q * 256 + t;          // 0..511
            int row = idx >> 2;             // 0..127
            int ks  = (idx & 3) * 8;        // 0,8,16,24
            uint32_t dsto = (uint32_t)(row * SASTRIDE + ks) * 2;  // 16B multiple
            size_t a_idx = (size_t)(i0 + row) * KP + k0 + ks;
            size_t b_idx = (size_t)(j0 + row) * KP + k0 + ks;
            cp16(base + dsto,                  d_Ah  + a_idx);
            cp16(base + TILE_BYTES + dsto,     d_Al  + a_idx);
            cp16(base + 2 * TILE_BYTES + dsto, d_WhT + b_idx);
            cp16(base + 3 * TILE_BYTES + dsto, d_WlT + b_idx);
        }
        asm volatile("cp.async.commit_group;");
    };

    load_stage(0, 0);

    for (int c = 0; c < NCH; c++) {
        int cur = c & 1;
        if (c + 1 < NCH) {
            load_stage(cur ^ 1, c + 1);
            asm volatile("cp.async.wait_group 1;");
        } else {
            asm volatile("cp.async.wait_group 0;");
        }
        __syncthreads();

        const uint32_t* Ah = (const uint32_t*)(sh + cur * (STAGE_BYTES / 2));
        const uint32_t* Al = Ah + TILE_HALFS / 2;
        const uint32_t* Bh = Al + TILE_HALFS / 2;
        const uint32_t* Bl = Bh + TILE_HALFS / 2;

#pragma unroll
        for (int kk = 0; kk < 2; kk++) {          // two k16 halves of the 32-chunk
            int kw = kk * 8;                      // offset in 32-bit words
            uint32_t ah[4][4], al[4][4];
#pragma unroll
            for (int mi = 0; mi < 4; mi++) {
                int m = wm + mi * 16 + qr;
                int w0 = m * SWSTRIDE + kw + qc, w1 = (m + 8) * SWSTRIDE + kw + qc;
                ah[mi][0] = Ah[w0];     ah[mi][1] = Ah[w1];
                ah[mi][2] = Ah[w0 + 4]; ah[mi][3] = Ah[w1 + 4];
                al[mi][0] = Al[w0];     al[mi][1] = Al[w1];
                al[mi][2] = Al[w0 + 4]; al[mi][3] = Al[w1 + 4];
            }
            uint32_t bh[4][2], bl[4][2];
#pragma unroll
            for (int ni = 0; ni < 4; ni++) {
                int n = wn + ni * 8 + qr;
                int w0 = n * SWSTRIDE + kw + qc;
                bh[ni][0] = Bh[w0]; bh[ni][1] = Bh[w0 + 4];
                bl[ni][0] = Bl[w0]; bl[ni][1] = Bl[w0 + 4];
            }
#pragma unroll
            for (int mi = 0; mi < 4; mi++)
#pragma unroll
                for (int ni = 0; ni < 4; ni++)
                    mma_f16(acc[mi][ni][0], acc[mi][ni][1], acc[mi][ni][2], acc[mi][ni][3],
                            ah[mi][0], ah[mi][1], ah[mi][2], ah[mi][3],
                            bh[ni][0], bh[ni][1]);
#pragma unroll
            for (int mi = 0; mi < 4; mi++)
#pragma unroll
                for (int ni = 0; ni < 4; ni++)
                    mma_f16(acc[mi][ni][0], acc[mi][ni][1], acc[mi][ni][2], acc[mi][ni][3],
                            al[mi][0], al[mi][1], al[mi][2], al[mi][3],
                            bh[ni][0], bh[ni][1]);
#pragma unroll
            for (int mi = 0; mi < 4; mi++)
#pragma unroll
                for (int ni = 0; ni < 4; ni++)
                    mma_f16(acc[mi][ni][0], acc[mi][ni][1], acc[mi][ni][2], acc[mi][ni][3],
                            ah[mi][0], ah[mi][1], ah[mi][2], ah[mi][3],
                            bl[ni][0], bl[ni][1]);
        }
        __syncthreads();
    }

    // epilogue: unscale + bias + relu, transposed stores into d_g[j][row]
#pragma unroll
    for (int mi = 0; mi < 4; mi++) {
        int r = i0 + wm + mi * 16 + qr;
#pragma unroll
        for (int ni = 0; ni < 4; ni++) {
            int j = j0 + wn + ni * 8 + 2 * qc;
            float bj0 = d_b1[j], bj1 = d_b1[j + 1];
            float* g0 = &d_g[(size_t)j * NROWS];
            float* g1 = &d_g[(size_t)(j + 1) * NROWS];
            g0[r]     = fmaxf(fmaf(acc[mi][ni][0], INV_WSCALE, bj0), 0.f);
            g1[r]     = fmaxf(fmaf(acc[mi][ni][1], INV_WSCALE, bj1), 0.f);
            g0[r + 8] = fmaxf(fmaf(acc[mi][ni][2], INV_WSCALE, bj0), 0.f);
            g1[r + 8] = fmaxf(fmaf(acc[mi][ni][3], INV_WSCALE, bj1), 0.f);
        }
    }
}

// ---------------- launch 5: logits + softmax + pred ----------------
__global__ __launch_bounds__(256) void k_pass2(const float* __restrict__ dec2_W,
                                               const float* __restrict__ dec2_b,
                                               float* __restrict__ out) {
    extern __shared__ float Ws[];
    int t = threadIdx.x;
    for (int i = t; i < HID * NC / 4; i += 256)
        ((float4*)Ws)[i] = ((const float4*)dec2_W)[i];
    __syncthreads();

    int r = blockIdx.x * 256 + t;
    float acc[NC];
#pragma unroll
    for (int c = 0; c < NC; c++) acc[c] = dec2_b[c];

#pragma unroll 4
    for (int k = 0; k < HID; k++) {
        float v = d_g[(size_t)k * NROWS + r];
        const float4* wr = (const float4*)&Ws[k * NC];
#pragma unroll
        for (int c4 = 0; c4 < NC / 4; c4++) {
            float4 w = wr[c4];
            acc[c4 * 4 + 0] += v * w.x;
            acc[c4 * 4 + 1] += v * w.y;
            acc[c4 * 4 + 2] += v * w.z;
            acc[c4 * 4 + 3] += v * w.w;
        }
    }

    float m = acc[1];
#pragma unroll
    for (int c = 2; c < NC; c++) m = fmaxf(m, acc[c]);
    float e[35], s = 0.f;
#pragma unroll
    for (int i = 0; i < 35; i++) { e[i] = expf(acc[1 + i] - m); s += e[i]; }
    float inv = 1.f / s;
#pragma unroll
    for (int i = 0; i < 35; i++) out[(size_t)r * 35 + i] = e[i] * inv;

    float best = e[1]; int bi = 1;
#pragma unroll
    for (int i = 2; i < 35; i++) if (e[i] > best) { best = e[i]; bi = i; }
    out[(size_t)NROWS * 35 + r]         = best * inv;
    out[(size_t)NROWS * 35 + NROWS + r] = (float)(bi + 1);
}

// ---------------- launch 6: human argmax per 64-row group ----------------
__global__ void k_pass3(float* __restrict__ out) {
    int g = blockIdx.x;
    int t = threadIdx.x;  // 64
    __shared__ float sv[64];
    __shared__ int   si[64];
    int r = g * PER + t;
    sv[t] = out[(size_t)r * 35 + 0];
    si[t] = t;
    __syncthreads();
    for (int off = 32; off > 0; off >>= 1) {
        if (t < off) {
            float v2 = sv[t + off]; int i2 = si[t + off];
            if (v2 > sv[t]) { sv[t] = v2; si[t] = i2; }
        }
        __syncthreads();
    }
    if (t == 0) {
        int h = g * PER + si[0];
        out[(size_t)NROWS * 35 + h]             = out[(size_t)h * 35 + 0];
        out[(size_t)NROWS * 35 + NROWS + h]     = 1.0f;
        out[(size_t)NROWS * 35 + 2 * NROWS + g] = (float)h;
    }
}

// ---------------- launcher ----------------
extern "C" void kernel_launch(void* const* d_in, const int* in_sizes, int n_in,
                              void* d_out, int out_size) {
    const float* distribution = (const float*)d_in[0];
    const float* features     = (const float*)d_in[1];
    const float* boxes        = (const float*)d_in[2];
    const float* obj_embed_W  = (const float*)d_in[3];
    const float* bn4_g        = (const float*)d_in[4];
    const float* bn4_b        = (const float*)d_in[5];
    const float* bn4_m        = (const float*)d_in[6];
    const float* bn4_v        = (const float*)d_in[7];
    const float* pos_W        = (const float*)d_in[8];
    const float* pos_b        = (const float*)d_in[9];
    const float* dec1_W       = (const float*)d_in[10];
    const float* dec1_b       = (const float*)d_in[11];
    const float* bn1k_g       = (const float*)d_in[12];
    const float* bn1k_b       = (const float*)d_in[13];
    const float* bn1k_m       = (const float*)d_in[14];
    const float* bn1k_v       = (const float*)d_in[15];
    const float* dec2_W       = (const float*)d_in[16];
    const float* dec2_b       = (const float*)d_in[17];
    float* out = (float*)d_out;

    k_prep<<<5, 256>>>(bn1k_g, bn1k_b, bn1k_m, bn1k_v, dec1_b,
                       bn4_g, bn4_b, bn4_m, bn4_v, pos_W, pos_b);
    k_weights<<<(HID * KP + 255) / 256, 256>>>(dec1_W, obj_embed_W);
    k_buildA<<<NROWS, 128>>>(features, distribution, boxes);

    cudaFuncSetAttribute(k_gemm1, cudaFuncAttributeMaxDynamicSharedMemorySize, SMEM_GEMM);
    k_gemm1<<<dim3(HID / BN, NROWS / BM), 256, SMEM_GEMM>>>();

    cudaFuncSetAttribute(k_pass2, cudaFuncAttributeMaxDynamicSharedMemorySize, HID * NC * 4);
    k_pass2<<<NROWS / 256, 256, HID * NC * 4>>>(dec2_W, dec2_b, out);
    k_pass3<<<NBLK, 64>>>(out);
}

// round 9
// speedup vs baseline: 1.8990x; 1.2237x over previous
#include <cuda_runtime.h>
#include <cuda_fp16.h>
#include <math.h>
#include <stdint.h>

#define NROWS 65536
#define PER   64
#define NBLK  1024
#define NC    36
#define OBJ   192
#define EMB   200
#define POSD  128
#define HID   1024
#define KEFF  355
#define KP    384          // 12 chunks of 32
#define EPS   1e-5f

#define WSCALE    64.f
#define INV_WSCALE 0.015625f

// GEMM1 tiling (legacy mma.sync m16n8k16 fp16, 3-pass compensated)
#define BM 128
#define BN 128
#define BKC 32
#define NCH (KP / BKC)            // 12
#define SASTRIDE 40               // halfs per SMEM row (80B rows, 16B-aligned)
#define SWSTRIDE (SASTRIDE / 2)   // 20 words per row
#define TILE_HALFS (128 * SASTRIDE)
#define TILE_BYTES (TILE_HALFS * 2)      // 10240
#define STAGE_BYTES (4 * TILE_BYTES)     // Ah, Al, Bh, Bl = 40960
#define W2_BYTES (128 * NC * 4)          // 18432
#define SMEM_GEMM (2 * STAGE_BYTES + W2_BYTES)   // 100352
#define GSTRIDE 133                      // gbuf row stride (floats), conflict-free

#define NJT (HID / BN)            // 8 j-tiles -> 8 logit partials

// ---------------- device scratch ----------------
__device__ __half d_Ah[(size_t)NROWS * KP];   // A hi (fp16)
__device__ __half d_Al[(size_t)NROWS * KP];   // A lo (fp16 residual)
__device__ __half d_WhT[(size_t)HID * KP];    // folded W*64 hi, transposed [j][k]
__device__ __half d_WlT[(size_t)HID * KP];    // folded W*64 lo, transposed [j][k]
__device__ float  d_b1[HID];
__device__ float  d_a[HID];
__device__ float  d_PW[4 * POSD];
__device__ float  d_pb[POSD];
__device__ float  d_part[(size_t)NJT * NC * NROWS];  // partial logits [jt][c][row]

// ---------------- launch 1: fused prep (bn folds) ----------------
__global__ void k_prep(const float* __restrict__ bn1k_g, const float* __restrict__ bn1k_b,
                       const float* __restrict__ bn1k_m, const float* __restrict__ bn1k_v,
                       const float* __restrict__ dec1_b,
                       const float* __restrict__ g4, const float* __restrict__ b4,
                       const float* __restrict__ m4, const float* __restrict__ v4,
                       const float* __restrict__ pos_W, const float* __restrict__ pos_b) {
    int b = blockIdx.x, t = threadIdx.x;
    if (b < 4) {
        int j = b * 256 + t;
        float a = bn1k_g[j] * rsqrtf(bn1k_v[j] + EPS);
        float c = bn1k_b[j] - bn1k_m[j] * a;
        d_a[j]  = a;
        d_b1[j] = dec1_b[j] * a + c;
    } else if (t < POSD) {
        int j = t;
        float s[4], tt[4];
#pragma unroll
        for (int k = 0; k < 4; k++) {
            s[k]  = g4[k] * rsqrtf(v4[k] + EPS);
            tt[k] = b4[k] - m4[k] * s[k];
        }
        float pb = pos_b[j];
#pragma unroll
        for (int k = 0; k < 4; k++) {
            float w = pos_W[k * POSD + j];
            d_PW[k * POSD + j] = s[k] * w;
            pb += tt[k] * w;
        }
        d_pb[j] = pb;
    }
}

// ---------------- launch 2: fold W (incl. obj_embed GEMM), scale, split fp16 ----------------
__global__ void k_weights(const float* __restrict__ dec1_W,
                          const float* __restrict__ obj_embed_W) {
    int idx = blockIdx.x * 256 + threadIdx.x;   // over [j][k], HID*KP
    if (idx >= HID * KP) return;
    int j = idx / KP, k = idx % KP;
    float v;
    if (k < OBJ) {
        v = dec1_W[(size_t)k * HID + j];
    } else if (k < OBJ + 35) {
        int e = k - OBJ;
        const float* er = obj_embed_W + e * EMB;
        float s = 0.f;
#pragma unroll 8
        for (int kk = 0; kk < EMB; kk++)
            s += er[kk] * dec1_W[(size_t)(OBJ + kk) * HID + j];
        v = s;
    } else if (k < KEFF) {
        v = dec1_W[(size_t)(OBJ + EMB + (k - (OBJ + 35))) * HID + j];
    } else {
        v = 0.f;
    }
    v *= d_a[j] * WSCALE;
    __half h = __float2half_rn(v);
    d_WhT[idx] = h;
    d_WlT[idx] = __float2half_rn(v - __half2float(h));
}

// ---------------- launch 3: build fused A, pre-split fp16 ----------------
__global__ void k_buildA(const float* __restrict__ features,
                         const float* __restrict__ distribution,
                         const float* __restrict__ boxes) {
    int r = blockIdx.x;
    int j = threadIdx.x;  // 128
    size_t base = (size_t)r * KP;
    auto put = [&](int col, float v) {
        __half h = __float2half_rn(v);
        d_Ah[base + col] = h;
        d_Al[base + col] = __float2half_rn(v - __half2float(h));
    };
    put(j, features[(size_t)r * OBJ + j]);
    if (j < 64) put(128 + j, features[(size_t)r * OBJ + 128 + j]);
    if (j < 35) put(OBJ + j, distribution[(size_t)r * 35 + j]);
    if (j >= 35 && j < 64) {
        d_Ah[base + 320 + j] = __float2half_rn(0.f);
        d_Al[base + 320 + j] = __float2half_rn(0.f);
    }
    float x1 = boxes[(size_t)r * 5 + 1], y1 = boxes[(size_t)r * 5 + 2];
    float x2 = boxes[(size_t)r * 5 + 3], y2 = boxes[(size_t)r * 5 + 4];
    float w = x2 - x1 + 1.f, h = y2 - y1 + 1.f;
    float c0 = x1 + 0.5f * w, c1 = y1 + 0.5f * h;
    float p = d_pb[j] + c0 * d_PW[j] + c1 * d_PW[POSD + j]
                     + w  * d_PW[2 * POSD + j] + h * d_PW[3 * POSD + j];
    put(OBJ + 35 + j, fmaxf(p, 0.f));
}

// ---------------- launch 4: GEMM1 + fused partial-logits epilogue ----------------
__device__ __forceinline__ void mma_f16(float& c0, float& c1, float& c2, float& c3,
                                        uint32_t a0, uint32_t a1, uint32_t a2, uint32_t a3,
                                        uint32_t b0, uint32_t b1) {
    asm volatile(
        "mma.sync.aligned.m16n8k16.row.col.f32.f16.f16.f32 "
        "{%0,%1,%2,%3}, {%4,%5,%6,%7}, {%8,%9}, {%0,%1,%2,%3};"
        : "+f"(c0), "+f"(c1), "+f"(c2), "+f"(c3)
        : "r"(a0), "r"(a1), "r"(a2), "r"(a3), "r"(b0), "r"(b1));
}
__device__ __forceinline__ void cp16(uint32_t dst, const void* src) {
    asm volatile("cp.async.ca.shared.global [%0], [%1], 16;" :: "r"(dst), "l"(src));
}

__global__ __launch_bounds__(256, 2) void k_gemm1(const float* __restrict__ dec2_W) {
    extern __shared__ __half sh[];
    uint32_t su = (uint32_t)__cvta_generic_to_shared(sh);

    int t    = threadIdx.x;
    int lane = t & 31;
    int warp = t >> 5;
    int qr   = lane >> 2;
    int qc   = lane & 3;
    int wm   = (warp >> 2) * 64;
    int wn   = (warp & 3) * 32;
    int i0   = blockIdx.y * BM;
    int j0   = blockIdx.x * BN;

    float acc[4][4][4];
#pragma unroll
    for (int mi = 0; mi < 4; mi++)
#pragma unroll
        for (int ni = 0; ni < 4; ni++)
#pragma unroll
            for (int q = 0; q < 4; q++) acc[mi][ni][q] = 0.f;

    auto load_stage = [&](int buf, int c) {
        int k0 = c * BKC;
        uint32_t base = su + buf * STAGE_BYTES;
#pragma unroll
        for (int q = 0; q < 2; q++) {
            int idx = q * 256 + t;
            int row = idx >> 2;
            int ks  = (idx & 3) * 8;
            uint32_t dsto = (uint32_t)(row * SASTRIDE + ks) * 2;
            size_t a_idx = (size_t)(i0 + row) * KP + k0 + ks;
            size_t b_idx = (size_t)(j0 + row) * KP + k0 + ks;
            cp16(base + dsto,                  d_Ah  + a_idx);
            cp16(base + TILE_BYTES + dsto,     d_Al  + a_idx);
            cp16(base + 2 * TILE_BYTES + dsto, d_WhT + b_idx);
            cp16(base + 3 * TILE_BYTES + dsto, d_WlT + b_idx);
        }
        asm volatile("cp.async.commit_group;");
    };

    // W2 slice (128 k-rows x 36 cols, contiguous in dec2_W) + stage 0 -> group 0
    {
        const float* w2src = dec2_W + (size_t)j0 * NC;
        uint32_t w2dst = su + 2 * STAGE_BYTES;
        for (int i = t; i < W2_BYTES / 16; i += 256)
            cp16(w2dst + i * 16, w2src + i * 4);
    }
    load_stage(0, 0);

    for (int c = 0; c < NCH; c++) {
        int cur = c & 1;
        if (c + 1 < NCH) {
            load_stage(cur ^ 1, c + 1);
            asm volatile("cp.async.wait_group 1;");
        } else {
            asm volatile("cp.async.wait_group 0;");
        }
        __syncthreads();

        const uint32_t* Ah = (const uint32_t*)(sh + cur * (STAGE_BYTES / 2));
        const uint32_t* Al = Ah + TILE_HALFS / 2;
        const uint32_t* Bh = Al + TILE_HALFS / 2;
        const uint32_t* Bl = Bh + TILE_HALFS / 2;

#pragma unroll
        for (int kk = 0; kk < 2; kk++) {
            int kw = kk * 8;
            uint32_t ah[4][4], al[4][4];
#pragma unroll
            for (int mi = 0; mi < 4; mi++) {
                int m = wm + mi * 16 + qr;
                int w0 = m * SWSTRIDE + kw + qc, w1 = (m + 8) * SWSTRIDE + kw + qc;
                ah[mi][0] = Ah[w0];     ah[mi][1] = Ah[w1];
                ah[mi][2] = Ah[w0 + 4]; ah[mi][3] = Ah[w1 + 4];
                al[mi][0] = Al[w0];     al[mi][1] = Al[w1];
                al[mi][2] = Al[w0 + 4]; al[mi][3] = Al[w1 + 4];
            }
            uint32_t bh[4][2], bl[4][2];
#pragma unroll
            for (int ni = 0; ni < 4; ni++) {
                int n = wn + ni * 8 + qr;
                int w0 = n * SWSTRIDE + kw + qc;
                bh[ni][0] = Bh[w0]; bh[ni][1] = Bh[w0 + 4];
                bl[ni][0] = Bl[w0]; bl[ni][1] = Bl[w0 + 4];
            }
#pragma unroll
            for (int mi = 0; mi < 4; mi++)
#pragma unroll
                for (int ni = 0; ni < 4; ni++)
                    mma_f16(acc[mi][ni][0], acc[mi][ni][1], acc[mi][ni][2], acc[mi][ni][3],
                            ah[mi][0], ah[mi][1], ah[mi][2], ah[mi][3],
                            bh[ni][0], bh[ni][1]);
#pragma unroll
            for (int mi = 0; mi < 4; mi++)
#pragma unroll
                for (int ni = 0; ni < 4; ni++)
                    mma_f16(acc[mi][ni][0], acc[mi][ni][1], acc[mi][ni][2], acc[mi][ni][3],
                            al[mi][0], al[mi][1], al[mi][2], al[mi][3],
                            bh[ni][0], bh[ni][1]);
#pragma unroll
            for (int mi = 0; mi < 4; mi++)
#pragma unroll
                for (int ni = 0; ni < 4; ni++)
                    mma_f16(acc[mi][ni][0], acc[mi][ni][1], acc[mi][ni][2], acc[mi][ni][3],
                            ah[mi][0], ah[mi][1], ah[mi][2], ah[mi][3],
                            bl[ni][0], bl[ni][1]);
        }
        __syncthreads();
    }

    // ---- fused epilogue: stage g tile in SMEM, then partial logits ----
    float* gbuf  = (float*)sh;                             // 128 x GSTRIDE floats (68 KB, stage reuse)
    const float* W2s = (const float*)(sh + STAGE_BYTES);   // = byte offset 2*STAGE_BYTES

#pragma unroll
    for (int mi = 0; mi < 4; mi++) {
        int rl = wm + mi * 16 + qr;
#pragma unroll
        for (int ni = 0; ni < 4; ni++) {
            int jl = wn + ni * 8 + 2 * qc;
            float bj0 = d_b1[j0 + jl], bj1 = d_b1[j0 + jl + 1];
            gbuf[rl * GSTRIDE + jl]           = fmaxf(fmaf(acc[mi][ni][0], INV_WSCALE, bj0), 0.f);
            gbuf[rl * GSTRIDE + jl + 1]       = fmaxf(fmaf(acc[mi][ni][1], INV_WSCALE, bj1), 0.f);
            gbuf[(rl + 8) * GSTRIDE + jl]     = fmaxf(fmaf(acc[mi][ni][2], INV_WSCALE, bj0), 0.f);
            gbuf[(rl + 8) * GSTRIDE + jl + 1] = fmaxf(fmaf(acc[mi][ni][3], INV_WSCALE, bj1), 0.f);
        }
    }
    __syncthreads();

    {
        int row = t & 127;
        int ch  = t >> 7;                  // 0: cols 0..17, 1: cols 18..35
        float accl[18];
#pragma unroll
        for (int c = 0; c < 18; c++) accl[c] = 0.f;
#pragma unroll 4
        for (int k = 0; k < 128; k++) {
            float v = gbuf[row * GSTRIDE + k];
            const float2* w2 = (const float2*)(W2s + k * NC + ch * 18);  // 8B-aligned
#pragma unroll
            for (int c2 = 0; c2 < 9; c2++) {
                float2 w = w2[c2];
                accl[2 * c2]     = fmaf(v, w.x, accl[2 * c2]);
                accl[2 * c2 + 1] = fmaf(v, w.y, accl[2 * c2 + 1]);
            }
        }
        size_t r_g = (size_t)(i0 + row);
#pragma unroll
        for (int c = 0; c < 18; c++)
            d_part[((size_t)blockIdx.x * NC + ch * 18 + c) * NROWS + r_g] = accl[c];
    }
}

// ---------------- launch 5: reduce partials + softmax + pred ----------------
__global__ __launch_bounds__(256) void k_pass2(const float* __restrict__ dec2_b,
                                               float* __restrict__ out) {
    int r = blockIdx.x * 256 + threadIdx.x;
    float acc[NC];
#pragma unroll
    for (int c = 0; c < NC; c++) acc[c] = dec2_b[c];

#pragma unroll 4
    for (int p = 0; p < NJT; p++)
#pragma unroll
        for (int c = 0; c < NC; c++)
            acc[c] += d_part[((size_t)p * NC + c) * NROWS + r];

    float m = acc[1];
#pragma unroll
    for (int c = 2; c < NC; c++) m = fmaxf(m, acc[c]);
    float e[35], s = 0.f;
#pragma unroll
    for (int i = 0; i < 35; i++) { e[i] = expf(acc[1 + i] - m); s += e[i]; }
    float inv = 1.f / s;
#pragma unroll
    for (int i = 0; i < 35; i++) out[(size_t)r * 35 + i] = e[i] * inv;

    float best = e[1]; int bi = 1;
#pragma unroll
    for (int i = 2; i < 35; i++) if (e[i] > best) { best = e[i]; bi = i; }
    out[(size_t)NROWS * 35 + r]         = best * inv;
    out[(size_t)NROWS * 35 + NROWS + r] = (float)(bi + 1);
}

// ---------------- launch 6: human argmax per 64-row group ----------------
__global__ void k_pass3(float* __restrict__ out) {
    int g = blockIdx.x;
    int t = threadIdx.x;  // 64
    __shared__ float sv[64];
    __shared__ int   si[64];
    int r = g * PER + t;
    sv[t] = out[(size_t)r * 35 + 0];
    si[t] = t;
    __syncthreads();
    for (int off = 32; off > 0; off >>= 1) {
        if (t < off) {
            float v2 = sv[t + off]; int i2 = si[t + off];
            if (v2 > sv[t]) { sv[t] = v2; si[t] = i2; }
        }
        __syncthreads();
    }
    if (t == 0) {
        int h = g * PER + si[0];
        out[(size_t)NROWS * 35 + h]             = out[(size_t)h * 35 + 0];
        out[(size_t)NROWS * 35 + NROWS + h]     = 1.0f;
        out[(size_t)NROWS * 35 + 2 * NROWS + g] = (float)h;
    }
}

// ---------------- launcher ----------------
extern "C" void kernel_launch(void* const* d_in, const int* in_sizes, int n_in,
                              void* d_out, int out_size) {
    const float* distribution = (const float*)d_in[0];
    const float* features     = (const float*)d_in[1];
    const float* boxes        = (const float*)d_in[2];
    const float* obj_embed_W  = (const float*)d_in[3];
    const float* bn4_g        = (const float*)d_in[4];
    const float* bn4_b        = (const float*)d_in[5];
    const float* bn4_m        = (const float*)d_in[6];
    const float* bn4_v        = (const float*)d_in[7];
    const float* pos_W        = (const float*)d_in[8];
    const float* pos_b        = (const float*)d_in[9];
    const float* dec1_W       = (const float*)d_in[10];
    const float* dec1_b       = (const float*)d_in[11];
    const float* bn1k_g       = (const float*)d_in[12];
    const float* bn1k_b       = (const float*)d_in[13];
    const float* bn1k_m       = (const float*)d_in[14];
    const float* bn1k_v       = (const float*)d_in[15];
    const float* dec2_W       = (const float*)d_in[16];
    const float* dec2_b       = (const float*)d_in[17];
    float* out = (float*)d_out;

    k_prep<<<5, 256>>>(bn1k_g, bn1k_b, bn1k_m, bn1k_v, dec1_b,
                       bn4_g, bn4_b, bn4_m, bn4_v, pos_W, pos_b);
    k_weights<<<(HID * KP + 255) / 256, 256>>>(dec1_W, obj_embed_W);
    k_buildA<<<NROWS, 128>>>(features, distribution, boxes);

    cudaFuncSetAttribute(k_gemm1, cudaFuncAttributeMaxDynamicSharedMemorySize, SMEM_GEMM);
    k_gemm1<<<dim3(HID / BN, NROWS / BM), 256, SMEM_GEMM>>>(dec2_W);

    k_pass2<<<NROWS / 256, 256>>>(dec2_b, out);
    k_pass3<<<NBLK, 64>>>(out);
}

// round 10
// speedup vs baseline: 2.1484x; 1.1313x over previous
#include <cuda_runtime.h>
#include <cuda_fp16.h>
#include <math.h>
#include <stdint.h>

#define NROWS 65536
#define PER   64
#define NBLK  1024
#define NC    36
#define NCP   40           // padded logits cols for mma (x8)
#define OBJ   192
#define EMB   200
#define POSD  128
#define HID   1024
#define KEFF  355
#define KP    384          // 12 chunks of 32
#define EPS   1e-5f

#define WSCALE    64.f
#define INV_WSCALE 0.015625f

// GEMM1 tiling (legacy mma.sync m16n8k16 fp16, 3-pass compensated)
#define BM 128
#define BN 128
#define BKC 32
#define NCH (KP / BKC)            // 12
#define SASTRIDE 40               // halfs per SMEM row (80B rows, 16B-aligned)
#define SWSTRIDE (SASTRIDE / 2)   // 20 words per row
#define TILE_HALFS (128 * SASTRIDE)
#define TILE_BYTES (TILE_HALFS * 2)      // 10240
#define STAGE_BYTES (4 * TILE_BYTES)     // Ah, Al, Bh, Bl = 40960

// epilogue layout
#define GSTRH 136                        // halves per g row (68 words) -> conflict-free
#define GH_WORDS (128 * GSTRH / 2)       // 8704 words per g buffer
#define W2_TILE_BYTES (NCP * GSTRH * 2)  // 10880
#define W2H_OFF (2 * STAGE_BYTES)                    // 81920
#define W2L_OFF (W2H_OFF + W2_TILE_BYTES)            // 92800
#define SB1_OFF (W2L_OFF + W2_TILE_BYTES)            // 103680
#define SMEM_GEMM (SB1_OFF + 512)                    // 104192

#define NJT (HID / BN)            // 8 j-tiles -> 8 logit partials

// ---------------- device scratch ----------------
__device__ __half d_Ah[(size_t)NROWS * KP];
__device__ __half d_Al[(size_t)NROWS * KP];
__device__ __half d_WhT[(size_t)HID * KP];    // folded W*64 hi, [j][k]
__device__ __half d_WlT[(size_t)HID * KP];    // folded W*64 lo, [j][k]
__device__ __half d_W2h[(size_t)NCP * HID];   // dec2_W^T*64 hi, [c][j]
__device__ __half d_W2l[(size_t)NCP * HID];   // dec2_W^T*64 lo, [c][j]
__device__ float  d_b1[HID];
__device__ float  d_a[HID];
__device__ float  d_PW[4 * POSD];
__device__ float  d_pb[POSD];
__device__ float  d_part[(size_t)NJT * NC * NROWS];  // partial logits [jt][c][row]

// ---------------- launch 1: fused prep (bn folds) ----------------
__global__ void k_prep(const float* __restrict__ bn1k_g, const float* __restrict__ bn1k_b,
                       const float* __restrict__ bn1k_m, const float* __restrict__ bn1k_v,
                       const float* __restrict__ dec1_b,
                       const float* __restrict__ g4, const float* __restrict__ b4,
                       const float* __restrict__ m4, const float* __restrict__ v4,
                       const float* __restrict__ pos_W, const float* __restrict__ pos_b) {
    int b = blockIdx.x, t = threadIdx.x;
    if (b < 4) {
        int j = b * 256 + t;
        float a = bn1k_g[j] * rsqrtf(bn1k_v[j] + EPS);
        float c = bn1k_b[j] - bn1k_m[j] * a;
        d_a[j]  = a;
        d_b1[j] = dec1_b[j] * a + c;
    } else if (t < POSD) {
        int j = t;
        float s[4], tt[4];
#pragma unroll
        for (int k = 0; k < 4; k++) {
            s[k]  = g4[k] * rsqrtf(v4[k] + EPS);
            tt[k] = b4[k] - m4[k] * s[k];
        }
        float pb = pos_b[j];
#pragma unroll
        for (int k = 0; k < 4; k++) {
            float w = pos_W[k * POSD + j];
            d_PW[k * POSD + j] = s[k] * w;
            pb += tt[k] * w;
        }
        d_pb[j] = pb;
    }
}

// ---------------- launch 2: fold W (incl. obj_embed GEMM), scale, split fp16 ----------------
__global__ void k_weights(const float* __restrict__ dec1_W,
                          const float* __restrict__ obj_embed_W) {
    int idx = blockIdx.x * 256 + threadIdx.x;
    if (idx >= HID * KP) return;
    int j = idx / KP, k = idx % KP;
    float v;
    if (k < OBJ) {
        v = dec1_W[(size_t)k * HID + j];
    } else if (k < OBJ + 35) {
        int e = k - OBJ;
        const float* er = obj_embed_W + e * EMB;
        float s = 0.f;
#pragma unroll 8
        for (int kk = 0; kk < EMB; kk++)
            s += er[kk] * dec1_W[(size_t)(OBJ + kk) * HID + j];
        v = s;
    } else if (k < KEFF) {
        v = dec1_W[(size_t)(OBJ + EMB + (k - (OBJ + 35))) * HID + j];
    } else {
        v = 0.f;
    }
    v *= d_a[j] * WSCALE;
    __half h = __float2half_rn(v);
    d_WhT[idx] = h;
    d_WlT[idx] = __float2half_rn(v - __half2float(h));
}

// ---------------- launch 2b: dec2_W^T scaled split ----------------
__global__ void k_weights2(const float* __restrict__ dec2_W) {
    int idx = blockIdx.x * 256 + threadIdx.x;   // over [c][j], NCP*HID
    if (idx >= NCP * HID) return;
    int c = idx / HID, j = idx % HID;
    float v = (c < NC) ? dec2_W[(size_t)j * NC + c] * WSCALE : 0.f;
    __half h = __float2half_rn(v);
    d_W2h[idx] = h;
    d_W2l[idx] = __float2half_rn(v - __half2float(h));
}

// ---------------- launch 3: build fused A, pre-split fp16 ----------------
__global__ void k_buildA(const float* __restrict__ features,
                         const float* __restrict__ distribution,
                         const float* __restrict__ boxes) {
    int r = blockIdx.x;
    int j = threadIdx.x;  // 128
    size_t base = (size_t)r * KP;
    auto put = [&](int col, float v) {
        __half h = __float2half_rn(v);
        d_Ah[base + col] = h;
        d_Al[base + col] = __float2half_rn(v - __half2float(h));
    };
    put(j, features[(size_t)r * OBJ + j]);
    if (j < 64) put(128 + j, features[(size_t)r * OBJ + 128 + j]);
    if (j < 35) put(OBJ + j, distribution[(size_t)r * 35 + j]);
    if (j >= 35 && j < 64) {
        d_Ah[base + 320 + j] = __float2half_rn(0.f);
        d_Al[base + 320 + j] = __float2half_rn(0.f);
    }
    float x1 = boxes[(size_t)r * 5 + 1], y1 = boxes[(size_t)r * 5 + 2];
    float x2 = boxes[(size_t)r * 5 + 3], y2 = boxes[(size_t)r * 5 + 4];
    float w = x2 - x1 + 1.f, h = y2 - y1 + 1.f;
    float c0 = x1 + 0.5f * w, c1 = y1 + 0.5f * h;
    float p = d_pb[j] + c0 * d_PW[j] + c1 * d_PW[POSD + j]
                     + w  * d_PW[2 * POSD + j] + h * d_PW[3 * POSD + j];
    put(OBJ + 35 + j, fmaxf(p, 0.f));
}

// ---------------- launch 4: GEMM1 + tensor-core logits epilogue ----------------
__device__ __forceinline__ void mma_f16(float& c0, float& c1, float& c2, float& c3,
                                        uint32_t a0, uint32_t a1, uint32_t a2, uint32_t a3,
                                        uint32_t b0, uint32_t b1) {
    asm volatile(
        "mma.sync.aligned.m16n8k16.row.col.f32.f16.f16.f32 "
        "{%0,%1,%2,%3}, {%4,%5,%6,%7}, {%8,%9}, {%0,%1,%2,%3};"
        : "+f"(c0), "+f"(c1), "+f"(c2), "+f"(c3)
        : "r"(a0), "r"(a1), "r"(a2), "r"(a3), "r"(b0), "r"(b1));
}
__device__ __forceinline__ void cp16(uint32_t dst, const void* src) {
    asm volatile("cp.async.ca.shared.global [%0], [%1], 16;" :: "r"(dst), "l"(src));
}
__device__ __forceinline__ uint32_t pack2(float x, float y) {
    __half2 h2 = __halves2half2(__float2half_rn(x), __float2half_rn(y));
    return *(uint32_t*)&h2;
}

__global__ __launch_bounds__(256, 2) void k_gemm1() {
    extern __shared__ __half sh[];
    uint32_t su = (uint32_t)__cvta_generic_to_shared(sh);

    int t    = threadIdx.x;
    int lane = t & 31;
    int warp = t >> 5;
    int qr   = lane >> 2;
    int qc   = lane & 3;
    int wm   = (warp >> 2) * 64;
    int wn   = (warp & 3) * 32;
    int i0   = blockIdx.y * BM;
    int j0   = blockIdx.x * BN;

    float acc[4][4][4];
#pragma unroll
    for (int mi = 0; mi < 4; mi++)
#pragma unroll
        for (int ni = 0; ni < 4; ni++)
#pragma unroll
            for (int q = 0; q < 4; q++) acc[mi][ni][q] = 0.f;

    auto load_stage = [&](int buf, int c) {
        int k0 = c * BKC;
        uint32_t base = su + buf * STAGE_BYTES;
#pragma unroll
        for (int q = 0; q < 2; q++) {
            int idx = q * 256 + t;
            int row = idx >> 2;
            int ks  = (idx & 3) * 8;
            uint32_t dsto = (uint32_t)(row * SASTRIDE + ks) * 2;
            size_t a_idx = (size_t)(i0 + row) * KP + k0 + ks;
            size_t b_idx = (size_t)(j0 + row) * KP + k0 + ks;
            cp16(base + dsto,                  d_Ah  + a_idx);
            cp16(base + TILE_BYTES + dsto,     d_Al  + a_idx);
            cp16(base + 2 * TILE_BYTES + dsto, d_WhT + b_idx);
            cp16(base + 3 * TILE_BYTES + dsto, d_WlT + b_idx);
        }
        asm volatile("cp.async.commit_group;");
    };

    // W2 hi/lo slices ([c][128] halves, row stride GSTRH) + b1 tile + stage 0
    {
        for (int i = t; i < NCP * 16; i += 256) {      // 640 cp16 per tile
            int c = i >> 4, ch = i & 15;
            uint32_t dsto = (uint32_t)(c * GSTRH * 2 + ch * 16);
            size_t src = (size_t)c * HID + j0 + ch * 8;
            cp16(su + W2H_OFF + dsto, d_W2h + src);
            cp16(su + W2L_OFF + dsto, d_W2l + src);
        }
        if (t < 128) ((float*)((char*)sh + SB1_OFF))[t] = d_b1[j0 + t];
    }
    load_stage(0, 0);

    for (int c = 0; c < NCH; c++) {
        int cur = c & 1;
        if (c + 1 < NCH) {
            load_stage(cur ^ 1, c + 1);
            asm volatile("cp.async.wait_group 1;");
        } else {
            asm volatile("cp.async.wait_group 0;");
        }
        __syncthreads();

        const uint32_t* Ah = (const uint32_t*)(sh + cur * (STAGE_BYTES / 2));
        const uint32_t* Al = Ah + TILE_HALFS / 2;
        const uint32_t* Bh = Al + TILE_HALFS / 2;
        const uint32_t* Bl = Bh + TILE_HALFS / 2;

#pragma unroll
        for (int kk = 0; kk < 2; kk++) {
            int kw = kk * 8;
            uint32_t ah[4][4], al[4][4];
#pragma unroll
            for (int mi = 0; mi < 4; mi++) {
                int m = wm + mi * 16 + qr;
                int w0 = m * SWSTRIDE + kw + qc, w1 = (m + 8) * SWSTRIDE + kw + qc;
                ah[mi][0] = Ah[w0];     ah[mi][1] = Ah[w1];
                ah[mi][2] = Ah[w0 + 4]; ah[mi][3] = Ah[w1 + 4];
                al[mi][0] = Al[w0];     al[mi][1] = Al[w1];
                al[mi][2] = Al[w0 + 4]; al[mi][3] = Al[w1 + 4];
            }
            uint32_t bh[4][2], bl[4][2];
#pragma unroll
            for (int ni = 0; ni < 4; ni++) {
                int n = wn + ni * 8 + qr;
                int w0 = n * SWSTRIDE + kw + qc;
                bh[ni][0] = Bh[w0]; bh[ni][1] = Bh[w0 + 4];
                bl[ni][0] = Bl[w0]; bl[ni][1] = Bl[w0 + 4];
            }
#pragma unroll
            for (int mi = 0; mi < 4; mi++)
#pragma unroll
                for (int ni = 0; ni < 4; ni++)
                    mma_f16(acc[mi][ni][0], acc[mi][ni][1], acc[mi][ni][2], acc[mi][ni][3],
                            ah[mi][0], ah[mi][1], ah[mi][2], ah[mi][3],
                            bh[ni][0], bh[ni][1]);
#pragma unroll
            for (int mi = 0; mi < 4; mi++)
#pragma unroll
                for (int ni = 0; ni < 4; ni++)
                    mma_f16(acc[mi][ni][0], acc[mi][ni][1], acc[mi][ni][2], acc[mi][ni][3],
                            al[mi][0], al[mi][1], al[mi][2], al[mi][3],
                            bh[ni][0], bh[ni][1]);
#pragma unroll
            for (int mi = 0; mi < 4; mi++)
#pragma unroll
                for (int ni = 0; ni < 4; ni++)
                    mma_f16(acc[mi][ni][0], acc[mi][ni][1], acc[mi][ni][2], acc[mi][ni][3],
                            ah[mi][0], ah[mi][1], ah[mi][2], ah[mi][3],
                            bl[ni][0], bl[ni][1]);
        }
        __syncthreads();
    }

    // ---- epilogue A: convert acc -> g (fp16 hi/lo) into SMEM (stage reuse) ----
    uint32_t* GHW = (uint32_t*)sh;              // 128 x 68 words
    uint32_t* GLW = GHW + GH_WORDS;
    const float* sb1 = (const float*)((char*)sh + SB1_OFF);

#pragma unroll
    for (int mi = 0; mi < 4; mi++) {
        int rl = wm + mi * 16 + qr;
#pragma unroll
        for (int ni = 0; ni < 4; ni++) {
            int jl = wn + ni * 8 + 2 * qc;
            float bj0 = sb1[jl], bj1 = sb1[jl + 1];
            float g00 = fmaxf(fmaf(acc[mi][ni][0], INV_WSCALE, bj0), 0.f);
            float g01 = fmaxf(fmaf(acc[mi][ni][1], INV_WSCALE, bj1), 0.f);
            float g10 = fmaxf(fmaf(acc[mi][ni][2], INV_WSCALE, bj0), 0.f);
            float g11 = fmaxf(fmaf(acc[mi][ni][3], INV_WSCALE, bj1), 0.f);
            uint32_t h0 = pack2(g00, g01), h1 = pack2(g10, g11);
            float r00 = g00 - __half2float(__low2half(*(__half2*)&h0));
            float r01 = g01 - __half2float(__high2half(*(__half2*)&h0));
            float r10 = g10 - __half2float(__low2half(*(__half2*)&h1));
            float r11 = g11 - __half2float(__high2half(*(__half2*)&h1));
            int w0 = rl * (GSTRH / 2) + (jl >> 1);
            int w1 = (rl + 8) * (GSTRH / 2) + (jl >> 1);
            GHW[w0] = h0;            GHW[w1] = h1;
            GLW[w0] = pack2(r00, r01);
            GLW[w1] = pack2(r10, r11);
        }
    }
    __syncthreads();

    // ---- epilogue B: logits partial via mma (each warp: 16 rows x 40 cols x K=128) ----
    {
        const uint32_t* W2H = (const uint32_t*)((char*)sh + W2H_OFF);
        const uint32_t* W2L = (const uint32_t*)((char*)sh + W2L_OFF);
        float a2[5][4];
#pragma unroll
        for (int ni = 0; ni < 5; ni++)
#pragma unroll
            for (int q = 0; q < 4; q++) a2[ni][q] = 0.f;

#pragma unroll
        for (int kt = 0; kt < 8; kt++) {
            int w0 = (16 * warp + qr) * (GSTRH / 2) + kt * 8 + qc;
            uint32_t ah0 = GHW[w0], ah1 = GHW[w0 + 8 * (GSTRH / 2)];
            uint32_t ah2 = GHW[w0 + 4], ah3 = GHW[w0 + 8 * (GSTRH / 2) + 4];
            uint32_t al0 = GLW[w0], al1 = GLW[w0 + 8 * (GSTRH / 2)];
            uint32_t al2 = GLW[w0 + 4], al3 = GLW[w0 + 8 * (GSTRH / 2) + 4];
#pragma unroll
            for (int ni = 0; ni < 5; ni++) {
                int v0 = (8 * ni + qr) * (GSTRH / 2) + kt * 8 + qc;
                uint32_t bh0 = W2H[v0], bh1 = W2H[v0 + 4];
                uint32_t bl0 = W2L[v0], bl1 = W2L[v0 + 4];
                mma_f16(a2[ni][0], a2[ni][1], a2[ni][2], a2[ni][3],
                        ah0, ah1, ah2, ah3, bh0, bh1);
                mma_f16(a2[ni][0], a2[ni][1], a2[ni][2], a2[ni][3],
                        al0, al1, al2, al3, bh0, bh1);
                mma_f16(a2[ni][0], a2[ni][1], a2[ni][2], a2[ni][3],
                        ah0, ah1, ah2, ah3, bl0, bl1);
            }
        }

        size_t r0 = (size_t)(i0 + 16 * warp + qr);
#pragma unroll
        for (int ni = 0; ni < 5; ni++) {
            int c = 8 * ni + 2 * qc;
            if (c < NC) {
                float* p = &d_part[((size_t)blockIdx.x * NC + c) * NROWS];
                p[r0]     = a2[ni][0] * INV_WSCALE;
                p[r0 + 8] = a2[ni][2] * INV_WSCALE;
            }
            if (c + 1 < NC) {
                float* p = &d_part[((size_t)blockIdx.x * NC + c + 1) * NROWS];
                p[r0]     = a2[ni][1] * INV_WSCALE;
                p[r0 + 8] = a2[ni][3] * INV_WSCALE;
            }
        }
    }
}

// ---------------- launch 5: reduce partials + softmax + pred ----------------
__global__ __launch_bounds__(256) void k_pass2(const float* __restrict__ dec2_b,
                                               float* __restrict__ out) {
    int r = blockIdx.x * 256 + threadIdx.x;
    float acc[NC];
#pragma unroll
    for (int c = 0; c < NC; c++) acc[c] = dec2_b[c];

#pragma unroll 4
    for (int p = 0; p < NJT; p++)
#pragma unroll
        for (int c = 0; c < NC; c++)
            acc[c] += d_part[((size_t)p * NC + c) * NROWS + r];

    float m = acc[1];
#pragma unroll
    for (int c = 2; c < NC; c++) m = fmaxf(m, acc[c]);
    float e[35], s = 0.f;
#pragma unroll
    for (int i = 0; i < 35; i++) { e[i] = expf(acc[1 + i] - m); s += e[i]; }
    float inv = 1.f / s;
#pragma unroll
    for (int i = 0; i < 35; i++) out[(size_t)r * 35 + i] = e[i] * inv;

    float best = e[1]; int bi = 1;
#pragma unroll
    for (int i = 2; i < 35; i++) if (e[i] > best) { best = e[i]; bi = i; }
    out[(size_t)NROWS * 35 + r]         = best * inv;
    out[(size_t)NROWS * 35 + NROWS + r] = (float)(bi + 1);
}

// ---------------- launch 6: human argmax per 64-row group ----------------
__global__ void k_pass3(float* __restrict__ out) {
    int g = blockIdx.x;
    int t = threadIdx.x;  // 64
    __shared__ float sv[64];
    __shared__ int   si[64];
    int r = g * PER + t;
    sv[t] = out[(size_t)r * 35 + 0];
    si[t] = t;
    __syncthreads();
    for (int off = 32; off > 0; off >>= 1) {
        if (t < off) {
            float v2 = sv[t + off]; int i2 = si[t + off];
            if (v2 > sv[t]) { sv[t] = v2; si[t] = i2; }
        }
        __syncthreads();
    }
    if (t == 0) {
        int h = g * PER + si[0];
        out[(size_t)NROWS * 35 + h]             = out[(size_t)h * 35 + 0];
        out[(size_t)NROWS * 35 + NROWS + h]     = 1.0f;
        out[(size_t)NROWS * 35 + 2 * NROWS + g] = (float)h;
    }
}

// ---------------- launcher ----------------
extern "C" void kernel_launch(void* const* d_in, const int* in_sizes, int n_in,
                              void* d_out, int out_size) {
    const float* distribution = (const float*)d_in[0];
    const float* features     = (const float*)d_in[1];
    const float* boxes        = (const float*)d_in[2];
    const float* obj_embed_W  = (const float*)d_in[3];
    const float* bn4_g        = (const float*)d_in[4];
    const float* bn4_b        = (const float*)d_in[5];
    const float* bn4_m        = (const float*)d_in[6];
    const float* bn4_v        = (const float*)d_in[7];
    const float* pos_W        = (const float*)d_in[8];
    const float* pos_b        = (const float*)d_in[9];
    const float* dec1_W       = (const float*)d_in[10];
    const float* dec1_b       = (const float*)d_in[11];
    const float* bn1k_g       = (const float*)d_in[12];
    const float* bn1k_b       = (const float*)d_in[13];
    const float* bn1k_m       = (const float*)d_in[14];
    const float* bn1k_v       = (const float*)d_in[15];
    const float* dec2_W       = (const float*)d_in[16];
    const float* dec2_b       = (const float*)d_in[17];
    float* out = (float*)d_out;

    k_prep<<<5, 256>>>(bn1k_g, bn1k_b, bn1k_m, bn1k_v, dec1_b,
                       bn4_g, bn4_b, bn4_m, bn4_v, pos_W, pos_b);
    k_weights<<<(HID * KP + 255) / 256, 256>>>(dec1_W, obj_embed_W);
    k_weights2<<<(NCP * HID + 255) / 256, 256>>>(dec2_W);
    k_buildA<<<NROWS, 128>>>(features, distribution, boxes);

    cudaFuncSetAttribute(k_gemm1, cudaFuncAttributeMaxDynamicSharedMemorySize, SMEM_GEMM);
    k_gemm1<<<dim3(HID / BN, NROWS / BM), 256, SMEM_GEMM>>>();

    k_pass2<<<NROWS / 256, 256>>>(dec2_b, out);
    k_pass3<<<NBLK, 64>>>(out);
}

// round 11
// speedup vs baseline: 2.4554x; 1.1429x over previous
#include <cuda_runtime.h>
#include <cuda_fp16.h>
#include <math.h>
#include <stdint.h>

#define NROWS 65536
#define PER   64
#define NBLK  1024
#define NC    36
#define NCP   40
#define OBJ   192
#define EMB   200
#define POSD  128
#define HID   1024
#define KEFF  355
#define KP    384
#define EPS   1e-5f

#define WSCALE    64.f
#define INV_WSCALE 0.015625f

#define BM 128
#define BN 128
#define BKC 32
#define NCH (KP / BKC)            // 12
#define SASTRIDE 40               // halfs per SMEM row (80B rows)
#define SWSTRIDE (SASTRIDE / 2)
#define TILE_HALFS (128 * SASTRIDE)
#define TILE_BYTES (TILE_HALFS * 2)      // 10240
#define STAGE_BYTES (4 * TILE_BYTES)     // 40960

#define GSTRH 136
#define GH_WORDS (128 * GSTRH / 2)
#define W2_TILE_BYTES (NCP * GSTRH * 2)
#define W2H_OFF (2 * STAGE_BYTES)
#define W2L_OFF (W2H_OFF + W2_TILE_BYTES)
#define SB1_OFF (W2L_OFF + W2_TILE_BYTES)
#define SMEM_GEMM (SB1_OFF + 512)

#define NJT (HID / BN)

// ---------------- device scratch ----------------
__device__ __half d_Ah[(size_t)NROWS * KP];
__device__ __half d_Al[(size_t)NROWS * KP];
__device__ __half d_WhT[(size_t)HID * KP];
__device__ __half d_WlT[(size_t)HID * KP];
__device__ __half d_W2h[(size_t)NCP * HID];
__device__ __half d_W2l[(size_t)NCP * HID];
__device__ float  d_b1[HID];
__device__ float  d_a[HID];
__device__ float  d_PW[4 * POSD];
__device__ float  d_pb[POSD];
__device__ float  d_part[(size_t)NJT * NC * NROWS];

// ---------------- launch 1: fused prep ----------------
__global__ void k_prep(const float* __restrict__ bn1k_g, const float* __restrict__ bn1k_b,
                       const float* __restrict__ bn1k_m, const float* __restrict__ bn1k_v,
                       const float* __restrict__ dec1_b,
                       const float* __restrict__ g4, const float* __restrict__ b4,
                       const float* __restrict__ m4, const float* __restrict__ v4,
                       const float* __restrict__ pos_W, const float* __restrict__ pos_b) {
    int b = blockIdx.x, t = threadIdx.x;
    if (b < 4) {
        int j = b * 256 + t;
        float a = bn1k_g[j] * rsqrtf(bn1k_v[j] + EPS);
        float c = bn1k_b[j] - bn1k_m[j] * a;
        d_a[j]  = a;
        d_b1[j] = dec1_b[j] * a + c;
    } else if (t < POSD) {
        int j = t;
        float s[4], tt[4];
#pragma unroll
        for (int k = 0; k < 4; k++) {
            s[k]  = g4[k] * rsqrtf(v4[k] + EPS);
            tt[k] = b4[k] - m4[k] * s[k];
        }
        float pb = pos_b[j];
#pragma unroll
        for (int k = 0; k < 4; k++) {
            float w = pos_W[k * POSD + j];
            d_PW[k * POSD + j] = s[k] * w;
            pb += tt[k] * w;
        }
        d_pb[j] = pb;
    }
}

// ---------------- launch 2: fold W, scale, split fp16 ----------------
__global__ void k_weights(const float* __restrict__ dec1_W,
                          const float* __restrict__ obj_embed_W) {
    int idx = blockIdx.x * 256 + threadIdx.x;
    if (idx >= HID * KP) return;
    int j = idx / KP, k = idx % KP;
    float v;
    if (k < OBJ) {
        v = dec1_W[(size_t)k * HID + j];
    } else if (k < OBJ + 35) {
        int e = k - OBJ;
        const float* er = obj_embed_W + e * EMB;
        float s = 0.f;
#pragma unroll 8
        for (int kk = 0; kk < EMB; kk++)
            s += er[kk] * dec1_W[(size_t)(OBJ + kk) * HID + j];
        v = s;
    } else if (k < KEFF) {
        v = dec1_W[(size_t)(OBJ + EMB + (k - (OBJ + 35))) * HID + j];
    } else {
        v = 0.f;
    }
    v *= d_a[j] * WSCALE;
    __half h = __float2half_rn(v);
    d_WhT[idx] = h;
    d_WlT[idx] = __float2half_rn(v - __half2float(h));
}

// ---------------- launch 2b: dec2_W^T scaled split ----------------
__global__ void k_weights2(const float* __restrict__ dec2_W) {
    int idx = blockIdx.x * 256 + threadIdx.x;
    if (idx >= NCP * HID) return;
    int c = idx / HID, j = idx % HID;
    float v = (c < NC) ? dec2_W[(size_t)j * NC + c] * WSCALE : 0.f;
    __half h = __float2half_rn(v);
    d_W2h[idx] = h;
    d_W2l[idx] = __float2half_rn(v - __half2float(h));
}

// ---------------- launch 3: build fused A, pre-split fp16 ----------------
__global__ void k_buildA(const float* __restrict__ features,
                         const float* __restrict__ distribution,
                         const float* __restrict__ boxes) {
    int r = blockIdx.x;
    int j = threadIdx.x;
    size_t base = (size_t)r * KP;
    auto put = [&](int col, float v) {
        __half h = __float2half_rn(v);
        d_Ah[base + col] = h;
        d_Al[base + col] = __float2half_rn(v - __half2float(h));
    };
    put(j, features[(size_t)r * OBJ + j]);
    if (j < 64) put(128 + j, features[(size_t)r * OBJ + 128 + j]);
    if (j < 35) put(OBJ + j, distribution[(size_t)r * 35 + j]);
    if (j >= 35 && j < 64) {
        d_Ah[base + 320 + j] = __float2half_rn(0.f);
        d_Al[base + 320 + j] = __float2half_rn(0.f);
    }
    float x1 = boxes[(size_t)r * 5 + 1], y1 = boxes[(size_t)r * 5 + 2];
    float x2 = boxes[(size_t)r * 5 + 3], y2 = boxes[(size_t)r * 5 + 4];
    float w = x2 - x1 + 1.f, h = y2 - y1 + 1.f;
    float c0 = x1 + 0.5f * w, c1 = y1 + 0.5f * h;
    float p = d_pb[j] + c0 * d_PW[j] + c1 * d_PW[POSD + j]
                     + w  * d_PW[2 * POSD + j] + h * d_PW[3 * POSD + j];
    put(OBJ + 35 + j, fmaxf(p, 0.f));
}

// ---------------- launch 4: GEMM1 + tensor-core logits epilogue ----------------
__device__ __forceinline__ void mma_f16(float& c0, float& c1, float& c2, float& c3,
                                        uint32_t a0, uint32_t a1, uint32_t a2, uint32_t a3,
                                        uint32_t b0, uint32_t b1) {
    asm volatile(
        "mma.sync.aligned.m16n8k16.row.col.f32.f16.f16.f32 "
        "{%0,%1,%2,%3}, {%4,%5,%6,%7}, {%8,%9}, {%0,%1,%2,%3};"
        : "+f"(c0), "+f"(c1), "+f"(c2), "+f"(c3)
        : "r"(a0), "r"(a1), "r"(a2), "r"(a3), "r"(b0), "r"(b1));
}
__device__ __forceinline__ void cp16(uint32_t dst, const void* src) {
    asm volatile("cp.async.ca.shared.global [%0], [%1], 16;" :: "r"(dst), "l"(src));
}
__device__ __forceinline__ void ldm4(uint32_t& r0, uint32_t& r1, uint32_t& r2, uint32_t& r3,
                                     uint32_t a) {
    asm volatile("ldmatrix.sync.aligned.m8n8.x4.shared.b16 {%0,%1,%2,%3}, [%4];"
                 : "=r"(r0), "=r"(r1), "=r"(r2), "=r"(r3) : "r"(a));
}
__device__ __forceinline__ uint32_t pack2(float x, float y) {
    __half2 h2 = __halves2half2(__float2half_rn(x), __float2half_rn(y));
    return *(uint32_t*)&h2;
}

__global__ __launch_bounds__(256, 2) void k_gemm1() {
    extern __shared__ __half sh[];
    uint32_t su = (uint32_t)__cvta_generic_to_shared(sh);

    int t    = threadIdx.x;
    int lane = t & 31;
    int warp = t >> 5;
    int qr   = lane >> 2;
    int qc   = lane & 3;
    int wm   = (warp >> 2) * 64;
    int wn   = (warp & 3) * 32;
    int i0   = blockIdx.y * BM;
    int j0   = blockIdx.x * BN;

    // ldmatrix lane geometry
    int aRow  = wm + (lane & 15);             // + mi*16
    int aKoff = (lane >> 4) << 3;             // 0 or 8 halves
    int bRow  = wn + ((lane >> 4) << 3) + (lane & 7);   // + p*16
    int bKoff = lane & 8;

    float acc[4][4][4];
#pragma unroll
    for (int mi = 0; mi < 4; mi++)
#pragma unroll
        for (int ni = 0; ni < 4; ni++)
#pragma unroll
            for (int q = 0; q < 4; q++) acc[mi][ni][q] = 0.f;

    auto load_stage = [&](int buf, int c) {
        int k0 = c * BKC;
        uint32_t base = su + buf * STAGE_BYTES;
#pragma unroll
        for (int q = 0; q < 2; q++) {
            int idx = q * 256 + t;
            int row = idx >> 2;
            int ks  = (idx & 3) * 8;
            uint32_t dsto = (uint32_t)(row * SASTRIDE + ks) * 2;
            size_t a_idx = (size_t)(i0 + row) * KP + k0 + ks;
            size_t b_idx = (size_t)(j0 + row) * KP + k0 + ks;
            cp16(base + dsto,                  d_Ah  + a_idx);
            cp16(base + TILE_BYTES + dsto,     d_Al  + a_idx);
            cp16(base + 2 * TILE_BYTES + dsto, d_WhT + b_idx);
            cp16(base + 3 * TILE_BYTES + dsto, d_WlT + b_idx);
        }
        asm volatile("cp.async.commit_group;");
    };

    // W2 hi/lo slices + b1 tile + stage 0 (all in commit group 0)
    {
        for (int i = t; i < NCP * 16; i += 256) {
            int c = i >> 4, ch = i & 15;
            uint32_t dsto = (uint32_t)(c * GSTRH * 2 + ch * 16);
            size_t src = (size_t)c * HID + j0 + ch * 8;
            cp16(su + W2H_OFF + dsto, d_W2h + src);
            cp16(su + W2L_OFF + dsto, d_W2l + src);
        }
        if (t < 128) ((float*)((char*)sh + SB1_OFF))[t] = d_b1[j0 + t];
    }
    load_stage(0, 0);

    for (int c = 0; c < NCH; c++) {
        int cur = c & 1;
        asm volatile("cp.async.wait_group 0;");
        __syncthreads();
        if (c + 1 < NCH) load_stage(cur ^ 1, c + 1);   // overlaps with compute below

        uint32_t aBase = su + cur * STAGE_BYTES;
        uint32_t bBase = aBase + 2 * TILE_BYTES;

#pragma unroll
        for (int kk = 0; kk < 2; kk++) {
            int kw2 = kk * 16;
            uint32_t ah[4][4], al[4][4];
#pragma unroll
            for (int mi = 0; mi < 4; mi++) {
                uint32_t ad = aBase + (uint32_t)(((aRow + mi * 16) * SASTRIDE + kw2 + aKoff) * 2);
                ldm4(ah[mi][0], ah[mi][1], ah[mi][2], ah[mi][3], ad);
                ldm4(al[mi][0], al[mi][1], al[mi][2], al[mi][3], ad + TILE_BYTES);
            }
            uint32_t bh[4][2], bl[4][2];
#pragma unroll
            for (int p = 0; p < 2; p++) {
                uint32_t bd = bBase + (uint32_t)(((bRow + p * 16) * SASTRIDE + kw2 + bKoff) * 2);
                ldm4(bh[2 * p][0], bh[2 * p][1], bh[2 * p + 1][0], bh[2 * p + 1][1], bd);
                ldm4(bl[2 * p][0], bl[2 * p][1], bl[2 * p + 1][0], bl[2 * p + 1][1], bd + TILE_BYTES);
            }
#pragma unroll
            for (int mi = 0; mi < 4; mi++)
#pragma unroll
                for (int ni = 0; ni < 4; ni++)
                    mma_f16(acc[mi][ni][0], acc[mi][ni][1], acc[mi][ni][2], acc[mi][ni][3],
                            ah[mi][0], ah[mi][1], ah[mi][2], ah[mi][3],
                            bh[ni][0], bh[ni][1]);
#pragma unroll
            for (int mi = 0; mi < 4; mi++)
#pragma unroll
                for (int ni = 0; ni < 4; ni++)
                    mma_f16(acc[mi][ni][0], acc[mi][ni][1], acc[mi][ni][2], acc[mi][ni][3],
                            al[mi][0], al[mi][1], al[mi][2], al[mi][3],
                            bh[ni][0], bh[ni][1]);
#pragma unroll
            for (int mi = 0; mi < 4; mi++)
#pragma unroll
                for (int ni = 0; ni < 4; ni++)
                    mma_f16(acc[mi][ni][0], acc[mi][ni][1], acc[mi][ni][2], acc[mi][ni][3],
                            ah[mi][0], ah[mi][1], ah[mi][2], ah[mi][3],
                            bl[ni][0], bl[ni][1]);
        }
    }
    __syncthreads();   // mainloop done before stage buffers are reused for g

    // ---- epilogue A: acc -> g (fp16 hi/lo) in SMEM ----
    uint32_t* GHW = (uint32_t*)sh;
    uint32_t* GLW = GHW + GH_WORDS;
    const float* sb1 = (const float*)((char*)sh + SB1_OFF);

#pragma unroll
    for (int mi = 0; mi < 4; mi++) {
        int rl = wm + mi * 16 + qr;
#pragma unroll
        for (int ni = 0; ni < 4; ni++) {
            int jl = wn + ni * 8 + 2 * qc;
            float bj0 = sb1[jl], bj1 = sb1[jl + 1];
            float g00 = fmaxf(fmaf(acc[mi][ni][0], INV_WSCALE, bj0), 0.f);
            float g01 = fmaxf(fmaf(acc[mi][ni][1], INV_WSCALE, bj1), 0.f);
            float g10 = fmaxf(fmaf(acc[mi][ni][2], INV_WSCALE, bj0), 0.f);
            float g11 = fmaxf(fmaf(acc[mi][ni][3], INV_WSCALE, bj1), 0.f);
            uint32_t h0 = pack2(g00, g01), h1 = pack2(g10, g11);
            float r00 = g00 - __half2float(__low2half(*(__half2*)&h0));
            float r01 = g01 - __half2float(__high2half(*(__half2*)&h0));
            float r10 = g10 - __half2float(__low2half(*(__half2*)&h1));
            float r11 = g11 - __half2float(__high2half(*(__half2*)&h1));
            int w0 = rl * (GSTRH / 2) + (jl >> 1);
            int w1 = (rl + 8) * (GSTRH / 2) + (jl >> 1);
            GHW[w0] = h0;            GHW[w1] = h1;
            GLW[w0] = pack2(r00, r01);
            GLW[w1] = pack2(r10, r11);
        }
    }
    __syncthreads();

    // ---- epilogue B: logits partial via mma ----
    {
        const uint32_t* W2H = (const uint32_t*)((char*)sh + W2H_OFF);
        const uint32_t* W2L = (const uint32_t*)((char*)sh + W2L_OFF);
        float a2[5][4];
#pragma unroll
        for (int ni = 0; ni < 5; ni++)
#pragma unroll
            for (int q = 0; q < 4; q++) a2[ni][q] = 0.f;

#pragma unroll
        for (int kt = 0; kt < 8; kt++) {
            int w0 = (16 * warp + qr) * (GSTRH / 2) + kt * 8 + qc;
            uint32_t ah0 = GHW[w0], ah1 = GHW[w0 + 8 * (GSTRH / 2)];
            uint32_t ah2 = GHW[w0 + 4], ah3 = GHW[w0 + 8 * (GSTRH / 2) + 4];
            uint32_t al0 = GLW[w0], al1 = GLW[w0 + 8 * (GSTRH / 2)];
            uint32_t al2 = GLW[w0 + 4], al3 = GLW[w0 + 8 * (GSTRH / 2) + 4];
#pragma unroll
            for (int ni = 0; ni < 5; ni++) {
                int v0 = (8 * ni + qr) * (GSTRH / 2) + kt * 8 + qc;
                uint32_t bh0 = W2H[v0], bh1 = W2H[v0 + 4];
                uint32_t bl0 = W2L[v0], bl1 = W2L[v0 + 4];
                mma_f16(a2[ni][0], a2[ni][1], a2[ni][2], a2[ni][3],
                        ah0, ah1, ah2, ah3, bh0, bh1);
                mma_f16(a2[ni][0], a2[ni][1], a2[ni][2], a2[ni][3],
                        al0, al1, al2, al3, bh0, bh1);
                mma_f16(a2[ni][0], a2[ni][1], a2[ni][2], a2[ni][3],
                        ah0, ah1, ah2, ah3, bl0, bl1);
            }
        }

        size_t r0 = (size_t)(i0 + 16 * warp + qr);
#pragma unroll
        for (int ni = 0; ni < 5; ni++) {
            int c = 8 * ni + 2 * qc;
            if (c < NC) {
                float* p = &d_part[((size_t)blockIdx.x * NC + c) * NROWS];
                p[r0]     = a2[ni][0] * INV_WSCALE;
                p[r0 + 8] = a2[ni][2] * INV_WSCALE;
            }
            if (c + 1 < NC) {
                float* p = &d_part[((size_t)blockIdx.x * NC + c + 1) * NROWS];
                p[r0]     = a2[ni][1] * INV_WSCALE;
                p[r0 + 8] = a2[ni][3] * INV_WSCALE;
            }
        }
    }
}

// ---------------- launch 5: reduce partials + softmax + pred + human argmax ----------------
__global__ __launch_bounds__(256) void k_pass2(const float* __restrict__ dec2_b,
                                               float* __restrict__ out) {
    __shared__ float sv[256];
    __shared__ int   si[256];
    int t = threadIdx.x;
    int r = blockIdx.x * 256 + t;
    float acc[NC];
#pragma unroll
    for (int c = 0; c < NC; c++) acc[c] = dec2_b[c];

#pragma unroll 4
    for (int p = 0; p < NJT; p++)
#pragma unroll
        for (int c = 0; c < NC; c++)
            acc[c] += d_part[((size_t)p * NC + c) * NROWS + r];

    float m = acc[1];
#pragma unroll
    for (int c = 2; c < NC; c++) m = fmaxf(m, acc[c]);
    float e[35], s = 0.f;
#pragma unroll
    for (int i = 0; i < 35; i++) { e[i] = expf(acc[1 + i] - m); s += e[i]; }
    float inv = 1.f / s;
#pragma unroll
    for (int i = 0; i < 35; i++) out[(size_t)r * 35 + i] = e[i] * inv;

    float best = e[1]; int bi = 1;
#pragma unroll
    for (int i = 2; i < 35; i++) if (e[i] > best) { best = e[i]; bi = i; }
    float score = best * inv;
    float label = (float)(bi + 1);
    float d0 = e[0] * inv;            // dist col 0

    // human argmax per 64-row group (4 groups per block)
    sv[t] = d0;
    si[t] = t & 63;
    __syncthreads();
#pragma unroll
    for (int off = 32; off > 0; off >>= 1) {
        if ((t & 63) < off) {
            float v2 = sv[t + off]; int i2 = si[t + off];
            if (v2 > sv[t] || (v2 == sv[t] && i2 < si[t])) { sv[t] = v2; si[t] = i2; }
        }
        __syncthreads();
    }
    int base = t & ~63;
    int win  = si[base];
    if ((t & 63) == win) { score = d0; label = 1.0f; }
    out[(size_t)NROWS * 35 + r]         = score;
    out[(size_t)NROWS * 35 + NROWS + r] = label;
    if ((t & 63) == 0)
        out[(size_t)NROWS * 35 + 2 * NROWS + (r >> 6)] = (float)(blockIdx.x * 256 + base + win);
}

// ---------------- launcher ----------------
extern "C" void kernel_launch(void* const* d_in, const int* in_sizes, int n_in,
                              void* d_out, int out_size) {
    const float* distribution = (const float*)d_in[0];
    const float* features     = (const float*)d_in[1];
    const float* boxes        = (const float*)d_in[2];
    const float* obj_embed_W  = (const float*)d_in[3];
    const float* bn4_g        = (const float*)d_in[4];
    const float* bn4_b        = (const float*)d_in[5];
    const float* bn4_m        = (const float*)d_in[6];
    const float* bn4_v        = (const float*)d_in[7];
    const float* pos_W        = (const float*)d_in[8];
    const float* pos_b        = (const float*)d_in[9];
    const float* dec1_W       = (const float*)d_in[10];
    const float* dec1_b       = (const float*)d_in[11];
    const float* bn1k_g       = (const float*)d_in[12];
    const float* bn1k_b       = (const float*)d_in[13];
    const float* bn1k_m       = (const float*)d_in[14];
    const float* bn1k_v       = (const float*)d_in[15];
    const float* dec2_W       = (const float*)d_in[16];
    const float* dec2_b       = (const float*)d_in[17];
    float* out = (float*)d_out;

    k_prep<<<5, 256>>>(bn1k_g, bn1k_b, bn1k_m, bn1k_v, dec1_b,
                       bn4_g, bn4_b, bn4_m, bn4_v, pos_W, pos_b);
    k_weights<<<(HID * KP + 255) / 256, 256>>>(dec1_W, obj_embed_W);
    k_weights2<<<(NCP * HID + 255) / 256, 256>>>(dec2_W);
    k_buildA<<<NROWS, 128>>>(features, distribution, boxes);

    cudaFuncSetAttribute(k_gemm1, cudaFuncAttributeMaxDynamicSharedMemorySize, SMEM_GEMM);
    k_gemm1<<<dim3(HID / BN, NROWS / BM), 256, SMEM_GEMM>>>();

    k_pass2<<<NROWS / 256, 256>>>(dec2_b, out);
}

// round 12
// speedup vs baseline: 2.5529x; 1.0397x over previous
#include <cuda_runtime.h>
#include <cuda_fp16.h>
#include <math.h>
#include <stdint.h>

#define NROWS 65536
#define PER   64
#define NBLK  1024
#define NC    36
#define NCP   40
#define OBJ   192
#define EMB   200
#define POSD  128
#define HID   1024
#define KEFF  355
#define KP    384
#define EPS   1e-5f

#define WSCALE    64.f
#define INV_WSCALE 0.015625f

// GEMM1 tiling: 128x256 CTA tile, K-chunks of 64, 512 threads, 1 CTA/SM
#define BM 128
#define BN 256
#define BKC 64
#define NCH (KP / BKC)            // 6
#define SASTRIDE 72               // halves per SMEM row (144B, 16B-aligned)
#define ATILE_BYTES (128 * SASTRIDE * 2)   // 18432
#define BTILE_BYTES (256 * SASTRIDE * 2)   // 36864
#define STAGE_BYTES (2 * ATILE_BYTES + 2 * BTILE_BYTES)  // 110592

// epilogue overlay (inside stage buffers, used after mainloop)
#define GSTRH 264                          // halves per g row (132 words)
#define GH_WORDS (128 * GSTRH / 2)         // 16896 words = 67584 B
#define W2_TILE_BYTES (NCP * GSTRH * 2)    // 21120
#define W2H_OFF (2 * GH_WORDS * 4)                     // 135168
#define W2L_OFF (W2H_OFF + W2_TILE_BYTES)              // 156288
#define SB1_OFF (2 * STAGE_BYTES)                      // 221184 (outside stages)
#define SMEM_GEMM (SB1_OFF + 1024)                     // 222208

#define NJT (HID / BN)            // 4 partials

// ---------------- device scratch ----------------
__device__ __half d_Ah[(size_t)NROWS * KP];
__device__ __half d_Al[(size_t)NROWS * KP];
__device__ __half d_WhT[(size_t)HID * KP];
__device__ __half d_WlT[(size_t)HID * KP];
__device__ __half d_W2h[(size_t)NCP * HID];
__device__ __half d_W2l[(size_t)NCP * HID];
__device__ float  d_b1[HID];
__device__ float  d_a[HID];
__device__ float  d_PW[4 * POSD];
__device__ float  d_pb[POSD];
__device__ float  d_part[(size_t)NJT * NC * NROWS];

// ---------------- launch 1: fused prep ----------------
__global__ void k_prep(const float* __restrict__ bn1k_g, const float* __restrict__ bn1k_b,
                       const float* __restrict__ bn1k_m, const float* __restrict__ bn1k_v,
                       const float* __restrict__ dec1_b,
                       const float* __restrict__ g4, const float* __restrict__ b4,
                       const float* __restrict__ m4, const float* __restrict__ v4,
                       const float* __restrict__ pos_W, const float* __restrict__ pos_b) {
    int b = blockIdx.x, t = threadIdx.x;
    if (b < 4) {
        int j = b * 256 + t;
        float a = bn1k_g[j] * rsqrtf(bn1k_v[j] + EPS);
        float c = bn1k_b[j] - bn1k_m[j] * a;
        d_a[j]  = a;
        d_b1[j] = dec1_b[j] * a + c;
    } else if (t < POSD) {
        int j = t;
        float s[4], tt[4];
#pragma unroll
        for (int k = 0; k < 4; k++) {
            s[k]  = g4[k] * rsqrtf(v4[k] + EPS);
            tt[k] = b4[k] - m4[k] * s[k];
        }
        float pb = pos_b[j];
#pragma unroll
        for (int k = 0; k < 4; k++) {
            float w = pos_W[k * POSD + j];
            d_PW[k * POSD + j] = s[k] * w;
            pb += tt[k] * w;
        }
        d_pb[j] = pb;
    }
}

// ---------------- launch 2: fold W, scale, split fp16 ----------------
__global__ void k_weights(const float* __restrict__ dec1_W,
                          const float* __restrict__ obj_embed_W) {
    int idx = blockIdx.x * 256 + threadIdx.x;
    if (idx >= HID * KP) return;
    int j = idx / KP, k = idx % KP;
    float v;
    if (k < OBJ) {
        v = dec1_W[(size_t)k * HID + j];
    } else if (k < OBJ + 35) {
        int e = k - OBJ;
        const float* er = obj_embed_W + e * EMB;
        float s = 0.f;
#pragma unroll 8
        for (int kk = 0; kk < EMB; kk++)
            s += er[kk] * dec1_W[(size_t)(OBJ + kk) * HID + j];
        v = s;
    } else if (k < KEFF) {
        v = dec1_W[(size_t)(OBJ + EMB + (k - (OBJ + 35))) * HID + j];
    } else {
        v = 0.f;
    }
    v *= d_a[j] * WSCALE;
    __half h = __float2half_rn(v);
    d_WhT[idx] = h;
    d_WlT[idx] = __float2half_rn(v - __half2float(h));
}

// ---------------- launch 2b: dec2_W^T scaled split ----------------
__global__ void k_weights2(const float* __restrict__ dec2_W) {
    int idx = blockIdx.x * 256 + threadIdx.x;
    if (idx >= NCP * HID) return;
    int c = idx / HID, j = idx % HID;
    float v = (c < NC) ? dec2_W[(size_t)j * NC + c] * WSCALE : 0.f;
    __half h = __float2half_rn(v);
    d_W2h[idx] = h;
    d_W2l[idx] = __float2half_rn(v - __half2float(h));
}

// ---------------- launch 3: build fused A, pre-split fp16 ----------------
__global__ void k_buildA(const float* __restrict__ features,
                         const float* __restrict__ distribution,
                         const float* __restrict__ boxes) {
    int r = blockIdx.x;
    int j = threadIdx.x;
    size_t base = (size_t)r * KP;
    auto put = [&](int col, float v) {
        __half h = __float2half_rn(v);
        d_Ah[base + col] = h;
        d_Al[base + col] = __float2half_rn(v - __half2float(h));
    };
    put(j, features[(size_t)r * OBJ + j]);
    if (j < 64) put(128 + j, features[(size_t)r * OBJ + 128 + j]);
    if (j < 35) put(OBJ + j, distribution[(size_t)r * 35 + j]);
    if (j >= 35 && j < 64) {
        d_Ah[base + 320 + j] = __float2half_rn(0.f);
        d_Al[base + 320 + j] = __float2half_rn(0.f);
    }
    float x1 = boxes[(size_t)r * 5 + 1], y1 = boxes[(size_t)r * 5 + 2];
    float x2 = boxes[(size_t)r * 5 + 3], y2 = boxes[(size_t)r * 5 + 4];
    float w = x2 - x1 + 1.f, h = y2 - y1 + 1.f;
    float c0 = x1 + 0.5f * w, c1 = y1 + 0.5f * h;
    float p = d_pb[j] + c0 * d_PW[j] + c1 * d_PW[POSD + j]
                     + w  * d_PW[2 * POSD + j] + h * d_PW[3 * POSD + j];
    put(OBJ + 35 + j, fmaxf(p, 0.f));
}

// ---------------- launch 4: GEMM1 + tensor-core logits epilogue ----------------
__device__ __forceinline__ void mma_f16(float& c0, float& c1, float& c2, float& c3,
                                        uint32_t a0, uint32_t a1, uint32_t a2, uint32_t a3,
                                        uint32_t b0, uint32_t b1) {
    asm volatile(
        "mma.sync.aligned.m16n8k16.row.col.f32.f16.f16.f32 "
        "{%0,%1,%2,%3}, {%4,%5,%6,%7}, {%8,%9}, {%0,%1,%2,%3};"
        : "+f"(c0), "+f"(c1), "+f"(c2), "+f"(c3)
        : "r"(a0), "r"(a1), "r"(a2), "r"(a3), "r"(b0), "r"(b1));
}
__device__ __forceinline__ void cp16(uint32_t dst, const void* src) {
    asm volatile("cp.async.ca.shared.global [%0], [%1], 16;" :: "r"(dst), "l"(src));
}
__device__ __forceinline__ void ldm4(uint32_t& r0, uint32_t& r1, uint32_t& r2, uint32_t& r3,
                                     uint32_t a) {
    asm volatile("ldmatrix.sync.aligned.m8n8.x4.shared.b16 {%0,%1,%2,%3}, [%4];"
                 : "=r"(r0), "=r"(r1), "=r"(r2), "=r"(r3) : "r"(a));
}
__device__ __forceinline__ uint32_t pack2(float x, float y) {
    __half2 h2 = __halves2half2(__float2half_rn(x), __float2half_rn(y));
    return *(uint32_t*)&h2;
}

__global__ __launch_bounds__(512, 1) void k_gemm1() {
    extern __shared__ __half sh[];
    uint32_t su = (uint32_t)__cvta_generic_to_shared(sh);

    int t    = threadIdx.x;
    int lane = t & 31;
    int warp = t >> 5;            // 0..15
    int qr   = lane >> 2;
    int qc   = lane & 3;
    int wm   = (warp >> 3) * 64;  // 2 row groups
    int wn   = (warp & 7) * 32;   // 8 col groups
    int i0   = blockIdx.y * BM;
    int j0   = blockIdx.x * BN;

    // ldmatrix lane geometry
    int aRow  = wm + (lane & 15);
    int aKoff = (lane >> 4) << 3;
    int bRow  = wn + ((lane >> 4) << 3) + (lane & 7);
    int bKoff = lane & 8;

    float acc[4][4][4];
#pragma unroll
    for (int mi = 0; mi < 4; mi++)
#pragma unroll
        for (int ni = 0; ni < 4; ni++)
#pragma unroll
            for (int q = 0; q < 4; q++) acc[mi][ni][q] = 0.f;

    auto load_stage = [&](int buf, int c) {
        int k0 = c * BKC;
        uint32_t base = su + buf * STAGE_BYTES;
#pragma unroll
        for (int q = 0; q < 2; q++) {                 // A: 1024 cp16 per (hi|lo)
            int idx = q * 512 + t;
            int row = idx >> 3;                       // 0..127
            int ks  = (idx & 7) * 8;
            uint32_t dsto = (uint32_t)(row * SASTRIDE + ks) * 2;
            size_t a_idx = (size_t)(i0 + row) * KP + k0 + ks;
            cp16(base + dsto,               d_Ah + a_idx);
            cp16(base + ATILE_BYTES + dsto, d_Al + a_idx);
        }
#pragma unroll
        for (int q = 0; q < 4; q++) {                 // B: 2048 cp16 per (hi|lo)
            int idx = q * 512 + t;
            int row = idx >> 3;                       // 0..255
            int ks  = (idx & 7) * 8;
            uint32_t dsto = (uint32_t)(row * SASTRIDE + ks) * 2;
            size_t b_idx = (size_t)(j0 + row) * KP + k0 + ks;
            cp16(base + 2 * ATILE_BYTES + dsto,               d_WhT + b_idx);
            cp16(base + 2 * ATILE_BYTES + BTILE_BYTES + dsto, d_WlT + b_idx);
        }
        asm volatile("cp.async.commit_group;");
    };

    // b1 tile (outside stage buffers) + stage 0
    if (t < 256) ((float*)((char*)sh + SB1_OFF))[t] = d_b1[j0 + t];
    load_stage(0, 0);

    for (int c = 0; c < NCH; c++) {
        int cur = c & 1;
        asm volatile("cp.async.wait_group 0;");
        __syncthreads();
        if (c + 1 < NCH) load_stage(cur ^ 1, c + 1);

        uint32_t aBase = su + cur * STAGE_BYTES;
        uint32_t bBase = aBase + 2 * ATILE_BYTES;

#pragma unroll
        for (int kk = 0; kk < 4; kk++) {
            int kw2 = kk * 16;
            uint32_t ah[4][4], al[4][4];
#pragma unroll
            for (int mi = 0; mi < 4; mi++) {
                uint32_t ad = aBase + (uint32_t)(((aRow + mi * 16) * SASTRIDE + kw2 + aKoff) * 2);
                ldm4(ah[mi][0], ah[mi][1], ah[mi][2], ah[mi][3], ad);
                ldm4(al[mi][0], al[mi][1], al[mi][2], al[mi][3], ad + ATILE_BYTES);
            }
            uint32_t bh[4][2], bl[4][2];
#pragma unroll
            for (int p = 0; p < 2; p++) {
                uint32_t bd = bBase + (uint32_t)(((bRow + p * 16) * SASTRIDE + kw2 + bKoff) * 2);
                ldm4(bh[2 * p][0], bh[2 * p][1], bh[2 * p + 1][0], bh[2 * p + 1][1], bd);
                ldm4(bl[2 * p][0], bl[2 * p][1], bl[2 * p + 1][0], bl[2 * p + 1][1], bd + BTILE_BYTES);
            }
#pragma unroll
            for (int mi = 0; mi < 4; mi++)
#pragma unroll
                for (int ni = 0; ni < 4; ni++)
                    mma_f16(acc[mi][ni][0], acc[mi][ni][1], acc[mi][ni][2], acc[mi][ni][3],
                            ah[mi][0], ah[mi][1], ah[mi][2], ah[mi][3],
                            bh[ni][0], bh[ni][1]);
#pragma unroll
            for (int mi = 0; mi < 4; mi++)
#pragma unroll
                for (int ni = 0; ni < 4; ni++)
                    mma_f16(acc[mi][ni][0], acc[mi][ni][1], acc[mi][ni][2], acc[mi][ni][3],
                            al[mi][0], al[mi][1], al[mi][2], al[mi][3],
                            bh[ni][0], bh[ni][1]);
#pragma unroll
            for (int mi = 0; mi < 4; mi++)
#pragma unroll
                for (int ni = 0; ni < 4; ni++)
                    mma_f16(acc[mi][ni][0], acc[mi][ni][1], acc[mi][ni][2], acc[mi][ni][3],
                            ah[mi][0], ah[mi][1], ah[mi][2], ah[mi][3],
                            bl[ni][0], bl[ni][1]);
        }
    }
    __syncthreads();   // mainloop reads done before overlay reuse

    // ---- load W2 slices into overlay (freed stage space) ----
    for (int i = t; i < NCP * 32; i += 512) {
        int c = i >> 5, ch = i & 31;
        uint32_t dsto = (uint32_t)(c * GSTRH * 2 + ch * 16);
        size_t src = (size_t)c * HID + j0 + ch * 8;
        cp16(su + W2H_OFF + dsto, d_W2h + src);
        cp16(su + W2L_OFF + dsto, d_W2l + src);
    }
    asm volatile("cp.async.commit_group;");

    // ---- epilogue A: acc -> g (fp16 hi/lo) in SMEM overlay ----
    uint32_t* GHW = (uint32_t*)sh;
    uint32_t* GLW = GHW + GH_WORDS;
    const float* sb1 = (const float*)((char*)sh + SB1_OFF);

#pragma unroll
    for (int mi = 0; mi < 4; mi++) {
        int rl = wm + mi * 16 + qr;
#pragma unroll
        for (int ni = 0; ni < 4; ni++) {
            int jl = wn + ni * 8 + 2 * qc;
            float bj0 = sb1[jl], bj1 = sb1[jl + 1];
            float g00 = fmaxf(fmaf(acc[mi][ni][0], INV_WSCALE, bj0), 0.f);
            float g01 = fmaxf(fmaf(acc[mi][ni][1], INV_WSCALE, bj1), 0.f);
            float g10 = fmaxf(fmaf(acc[mi][ni][2], INV_WSCALE, bj0), 0.f);
            float g11 = fmaxf(fmaf(acc[mi][ni][3], INV_WSCALE, bj1), 0.f);
            uint32_t h0 = pack2(g00, g01), h1 = pack2(g10, g11);
            float r00 = g00 - __half2float(__low2half(*(__half2*)&h0));
            float r01 = g01 - __half2float(__high2half(*(__half2*)&h0));
            float r10 = g10 - __half2float(__low2half(*(__half2*)&h1));
            float r11 = g11 - __half2float(__high2half(*(__half2*)&h1));
            int w0 = rl * (GSTRH / 2) + (jl >> 1);
            int w1 = (rl + 8) * (GSTRH / 2) + (jl >> 1);
            GHW[w0] = h0;            GHW[w1] = h1;
            GLW[w0] = pack2(r00, r01);
            GLW[w1] = pack2(r10, r11);
        }
    }
    asm volatile("cp.async.wait_group 0;");
    __syncthreads();

    // ---- epilogue B: logits partial via mma (K=256 per CTA) ----
    {
        const uint32_t* W2H = (const uint32_t*)((char*)sh + W2H_OFF);
        const uint32_t* W2L = (const uint32_t*)((char*)sh + W2L_OFF);
        int wq    = warp & 7;                 // row group (16 rows)
        int nbase = (warp >> 3) * 3;          // warps 0-7: ni 0..2, 8-15: ni 3..4
        float a2[3][4];
#pragma unroll
        for (int nn = 0; nn < 3; nn++)
#pragma unroll
            for (int q = 0; q < 4; q++) a2[nn][q] = 0.f;

#pragma unroll
        for (int kt = 0; kt < 16; kt++) {
            int w0 = (16 * wq + qr) * (GSTRH / 2) + kt * 8 + qc;
            uint32_t ah0 = GHW[w0], ah1 = GHW[w0 + 8 * (GSTRH / 2)];
            uint32_t ah2 = GHW[w0 + 4], ah3 = GHW[w0 + 8 * (GSTRH / 2) + 4];
            uint32_t al0 = GLW[w0], al1 = GLW[w0 + 8 * (GSTRH / 2)];
            uint32_t al2 = GLW[w0 + 4], al3 = GLW[w0 + 8 * (GSTRH / 2) + 4];
#pragma unroll
            for (int nn = 0; nn < 3; nn++) {
                int ni = nbase + nn;
                if (ni < 5) {
                    int v0 = (8 * ni + qr) * (GSTRH / 2) + kt * 8 + qc;
                    uint32_t bh0 = W2H[v0], bh1 = W2H[v0 + 4];
                    uint32_t bl0 = W2L[v0], bl1 = W2L[v0 + 4];
                    mma_f16(a2[nn][0], a2[nn][1], a2[nn][2], a2[nn][3],
                            ah0, ah1, ah2, ah3, bh0, bh1);
                    mma_f16(a2[nn][0], a2[nn][1], a2[nn][2], a2[nn][3],
                            al0, al1, al2, al3, bh0, bh1);
                    mma_f16(a2[nn][0], a2[nn][1], a2[nn][2], a2[nn][3],
                            ah0, ah1, ah2, ah3, bl0, bl1);
                }
            }
        }

        size_t r0 = (size_t)(i0 + 16 * wq + qr);
#pragma unroll
        for (int nn = 0; nn < 3; nn++) {
            int ni = nbase + nn;
            if (ni < 5) {
                int c = 8 * ni + 2 * qc;
                if (c < NC) {
                    float* p = &d_part[((size_t)blockIdx.x * NC + c) * NROWS];
                    p[r0]     = a2[nn][0] * INV_WSCALE;
                    p[r0 + 8] = a2[nn][2] * INV_WSCALE;
                }
                if (c + 1 < NC) {
                    float* p = &d_part[((size_t)blockIdx.x * NC + c + 1) * NROWS];
                    p[r0]     = a2[nn][1] * INV_WSCALE;
                    p[r0 + 8] = a2[nn][3] * INV_WSCALE;
                }
            }
        }
    }
}

// ---------------- launch 5: reduce partials + softmax + pred + human argmax ----------------
__global__ __launch_bounds__(256) void k_pass2(const float* __restrict__ dec2_b,
                                               float* __restrict__ out) {
    __shared__ float sv[256];
    __shared__ int   si[256];
    int t = threadIdx.x;
    int r = blockIdx.x * 256 + t;
    float acc[NC];
#pragma unroll
    for (int c = 0; c < NC; c++) acc[c] = dec2_b[c];

#pragma unroll
    for (int p = 0; p < NJT; p++)
#pragma unroll
        for (int c = 0; c < NC; c++)
            acc[c] += d_part[((size_t)p * NC + c) * NROWS + r];

    float m = acc[1];
#pragma unroll
    for (int c = 2; c < NC; c++) m = fmaxf(m, acc[c]);
    float e[35], s = 0.f;
#pragma unroll
    for (int i = 0; i < 35; i++) { e[i] = expf(acc[1 + i] - m); s += e[i]; }
    float inv = 1.f / s;
#pragma unroll
    for (int i = 0; i < 35; i++) out[(size_t)r * 35 + i] = e[i] * inv;

    float best = e[1]; int bi = 1;
#pragma unroll
    for (int i = 2; i < 35; i++) if (e[i] > best) { best = e[i]; bi = i; }
    float score = best * inv;
    float label = (float)(bi + 1);
    float d0 = e[0] * inv;

    sv[t] = d0;
    si[t] = t & 63;
    __syncthreads();
#pragma unroll
    for (int off = 32; off > 0; off >>= 1) {
        if ((t & 63) < off) {
            float v2 = sv[t + off]; int i2 = si[t + off];
            if (v2 > sv[t] || (v2 == sv[t] && i2 < si[t])) { sv[t] = v2; si[t] = i2; }
        }
        __syncthreads();
    }
    int base = t & ~63;
    int win  = si[base];
    if ((t & 63) == win) { score = d0; label = 1.0f; }
    out[(size_t)NROWS * 35 + r]         = score;
    out[(size_t)NROWS * 35 + NROWS + r] = label;
    if ((t & 63) == 0)
        out[(size_t)NROWS * 35 + 2 * NROWS + (r >> 6)] = (float)(blockIdx.x * 256 + base + win);
}

// ---------------- launcher ----------------
extern "C" void kernel_launch(void* const* d_in, const int* in_sizes, int n_in,
                              void* d_out, int out_size) {
    const float* distribution = (const float*)d_in[0];
    const float* features     = (const float*)d_in[1];
    const float* boxes        = (const float*)d_in[2];
    const float* obj_embed_W  = (const float*)d_in[3];
    const float* bn4_g        = (const float*)d_in[4];
    const float* bn4_b        = (const float*)d_in[5];
    const float* bn4_m        = (const float*)d_in[6];
    const float* bn4_v        = (const float*)d_in[7];
    const float* pos_W        = (const float*)d_in[8];
    const float* pos_b        = (const float*)d_in[9];
    const float* dec1_W       = (const float*)d_in[10];
    const float* dec1_b       = (const float*)d_in[11];
    const float* bn1k_g       = (const float*)d_in[12];
    const float* bn1k_b       = (const float*)d_in[13];
    const float* bn1k_m       = (const float*)d_in[14];
    const float* bn1k_v       = (const float*)d_in[15];
    const float* dec2_W       = (const float*)d_in[16];
    const float* dec2_b       = (const float*)d_in[17];
    float* out = (float*)d_out;

    k_prep<<<5, 256>>>(bn1k_g, bn1k_b, bn1k_m, bn1k_v, dec1_b,
                       bn4_g, bn4_b, bn4_m, bn4_v, pos_W, pos_b);
    k_weights<<<(HID * KP + 255) / 256, 256>>>(dec1_W, obj_embed_W);
    k_weights2<<<(NCP * HID + 255) / 256, 256>>>(dec2_W);
    k_buildA<<<NROWS, 128>>>(features, distribution, boxes);

    cudaFuncSetAttribute(k_gemm1, cudaFuncAttributeMaxDynamicSharedMemorySize, SMEM_GEMM);
    k_gemm1<<<dim3(HID / BN, NROWS / BM), 512, SMEM_GEMM>>>();

    k_pass2<<<NROWS / 256, 256>>>(dec2_b, out);
}